// round 1
// baseline (speedup 1.0000x reference)
#include <cuda_runtime.h>
#include <math.h>

#define BB 8
#define C 64
#define H 128
#define W 128
#define HW (H*W)            // 16384
#define NPIX (BB*HW)        // 131072
#define CO_OFF 27
#define KIDX 576            // C*9
#define SWPAD 66            // padded row for [576][66] weight smem

// ---------------- scratch (no allocations allowed) ----------------
__device__ float g_xT[NPIX*C];           // x in NHWC
__device__ float g_off[BB*CO_OFF*HW];    // offset conv output (b,27,H,W)
__device__ float g_wcT[KIDX*C];          // w_conv transposed [idx][o]
__device__ float g_y[NPIX*C];            // result in NHWC before final transpose

// ---------------- NCHW -> NHWC transpose of x ----------------
__global__ void k_transpose_in(const float* __restrict__ x) {
    __shared__ float tile[32][33];
    int b  = blockIdx.z;
    int c0 = blockIdx.y * 32;
    int p0 = blockIdx.x * 32;
    int tx = threadIdx.x, ty = threadIdx.y;
#pragma unroll
    for (int i = 0; i < 4; i++)
        tile[ty + 8*i][tx] = x[(b*C + c0 + ty + 8*i)*HW + p0 + tx];
    __syncthreads();
#pragma unroll
    for (int i = 0; i < 4; i++)
        g_xT[(b*HW + p0 + ty + 8*i)*C + c0 + tx] = tile[tx][ty + 8*i];
}

// ---------------- NHWC -> NCHW transpose of y ----------------
__global__ void k_transpose_out(float* __restrict__ out) {
    __shared__ float tile[32][33];
    int b  = blockIdx.z;
    int c0 = blockIdx.y * 32;
    int p0 = blockIdx.x * 32;
    int tx = threadIdx.x, ty = threadIdx.y;
#pragma unroll
    for (int i = 0; i < 4; i++)
        tile[ty + 8*i][tx] = g_y[(b*HW + p0 + ty + 8*i)*C + c0 + tx];
    __syncthreads();
#pragma unroll
    for (int i = 0; i < 4; i++)
        out[(b*C + c0 + ty + 8*i)*HW + p0 + tx] = tile[tx][ty + 8*i];
}

// ---------------- transpose w_conv (64,576) -> (576,64) ----------------
__global__ void k_wtrans(const float* __restrict__ w_conv) {
    int i = blockIdx.x * blockDim.x + threadIdx.x;
    if (i < KIDX*C) {
        int o = i & 63, idx = i >> 6;
        g_wcT[i] = w_conv[o*KIDX + idx];
    }
}

// ---------------- offset-predictor 3x3 conv, pad 1 ----------------
__global__ __launch_bounds__(256) void k_offconv(
    const float* __restrict__ x, const float* __restrict__ w_off,
    const float* __restrict__ b_off)
{
    extern __shared__ float sw[];   // [c*9 + t][co] = w_off[co][c][t], 15552 floats
    for (int i = threadIdx.x; i < CO_OFF*KIDX; i += blockDim.x) {
        int co = i / KIDX;
        int ct = i % KIDX;
        sw[ct*CO_OFF + co] = w_off[i];     // coalesced read, stride-27 smem write (no conflicts)
    }
    __syncthreads();

    int pix = blockIdx.x * blockDim.x + threadIdx.x;
    int b = pix >> 14;
    int h = (pix >> 7) & 127;
    int w = pix & 127;

    float acc[CO_OFF];
#pragma unroll
    for (int co = 0; co < CO_OFF; co++) acc[co] = b_off[co];

    const float* xb = x + (size_t)b*C*HW;
    for (int c = 0; c < C; c++) {
        const float* xc = xb + c*HW;
        float xv[9];
#pragma unroll
        for (int t = 0; t < 9; t++) {
            int yy = h + t/3 - 1;
            int xx = w + t%3 - 1;
            bool v = (yy >= 0) && (yy < H) && (xx >= 0) && (xx < W);
            xv[t] = v ? xc[yy*W + xx] : 0.f;
        }
        const float* wp = sw + c*9*CO_OFF;
#pragma unroll
        for (int t = 0; t < 9; t++) {
#pragma unroll
            for (int co = 0; co < CO_OFF; co++)
                acc[co] += xv[t] * wp[t*CO_OFF + co];
        }
    }
    float* op = g_off + (size_t)b*CO_OFF*HW + h*W + w;
#pragma unroll
    for (int co = 0; co < CO_OFF; co++)
        op[co*HW] = acc[co];
}

// ---------------- fused bilinear sample + mask + 1x1 GEMM ----------------
// one warp per pixel iteration; lanes own 2 output channels (2*lane, 2*lane+1)
__global__ __launch_bounds__(512) void k_fused() {
    extern __shared__ float s_w[];          // [576][66] padded weights
    __shared__ float s_v[16*64];            // per-warp sampled-v staging
    const int tid  = threadIdx.x;
    const int lane = tid & 31;
    const int warp = tid >> 5;

    // stage transposed weights: coalesced global read, conflict-free smem write
    for (int i = tid; i < KIDX*C; i += blockDim.x) {
        int row = i >> 6, col = i & 63;
        s_w[row*SWPAD + col] = g_wcT[i];
    }
    __syncthreads();

    float* vbuf = s_v + warp*64;
    const int gwarp = blockIdx.x * (blockDim.x >> 5) + warp;
    const int nwarp = gridDim.x * (blockDim.x >> 5);
    const float2* xp2 = (const float2*)g_xT;

    for (int pix = gwarp; pix < NPIX; pix += nwarp) {
        int b = pix >> 14;
        int h = (pix >> 7) & 127;
        int w = pix & 127;

        // lanes 0..8: per-tap parameters
        float w00 = 0.f, w01 = 0.f, w10 = 0.f, w11 = 0.f;
        int p00 = 0, p01 = 0, p10 = 0, p11 = 0;
        if (lane < 9) {
            int base = (b*CO_OFF + lane)*HW + h*W + w;
            float o1 = g_off[base];
            float o2 = g_off[base +  9*HW];
            float mv = g_off[base + 18*HW];
            float mask = 1.f / (1.f + expf(-mv));
            int kh = lane / 3;
            int kw = lane - kh*3;
            float px = o1 + (float)(w + kw - 1);
            float py = o2 + (float)(h + kh - 1);
            float x0f = floorf(px), y0f = floorf(py);
            int x0 = (int)x0f, y0 = (int)y0f;
            float wx1 = px - x0f, wy1 = py - y0f;
            float wx0 = 1.f - wx1, wy0 = 1.f - wy1;
            float vx0 = (x0 >= 0   && x0 < W)     ? 1.f : 0.f;
            float vx1 = (x0 >= -1  && x0 + 1 < W) ? 1.f : 0.f;
            float vy0 = (y0 >= 0   && y0 < H)     ? 1.f : 0.f;
            float vy1 = (y0 >= -1  && y0 + 1 < H) ? 1.f : 0.f;
            w00 = wy0*wx0*mask*vy0*vx0;
            w01 = wy0*wx1*mask*vy0*vx1;
            w10 = wy1*wx0*mask*vy1*vx0;
            w11 = wy1*wx1*mask*vy1*vx1;
            int cx0 = min(max(x0, 0), W-1),   cx1 = min(max(x0+1, 0), W-1);
            int cy0 = min(max(y0, 0), H-1),   cy1 = min(max(y0+1, 0), H-1);
            int rb = b*HW;
            p00 = (rb + cy0*W + cx0) << 6;   // float index into g_xT
            p01 = (rb + cy0*W + cx1) << 6;
            p10 = (rb + cy1*W + cx0) << 6;
            p11 = (rb + cy1*W + cx1) << 6;
        }

        float2 acc = make_float2(0.f, 0.f);
#pragma unroll 1
        for (int k = 0; k < 9; k++) {
            float a00 = __shfl_sync(0xffffffffu, w00, k);
            float a01 = __shfl_sync(0xffffffffu, w01, k);
            float a10 = __shfl_sync(0xffffffffu, w10, k);
            float a11 = __shfl_sync(0xffffffffu, w11, k);
            int   q00 = __shfl_sync(0xffffffffu, p00, k);
            int   q01 = __shfl_sync(0xffffffffu, p01, k);
            int   q10 = __shfl_sync(0xffffffffu, p10, k);
            int   q11 = __shfl_sync(0xffffffffu, p11, k);

            float2 v00 = xp2[(q00 >> 1) + lane];
            float2 v01 = xp2[(q01 >> 1) + lane];
            float2 v10 = xp2[(q10 >> 1) + lane];
            float2 v11 = xp2[(q11 >> 1) + lane];
            float2 v;
            v.x = a00*v00.x + a01*v01.x + a10*v10.x + a11*v11.x;
            v.y = a00*v00.y + a01*v01.y + a10*v10.y + a11*v11.y;

            __syncwarp();                      // prev-iter readers done
            ((float2*)vbuf)[lane] = v;
            __syncwarp();

#pragma unroll 8
            for (int c = 0; c < 64; c++) {
                float vc = vbuf[c];                                   // broadcast
                float2 wv = *(const float2*)(s_w + (c*9 + k)*SWPAD + 2*lane);
                acc.x += vc * wv.x;
                acc.y += vc * wv.y;
            }
        }
        ((float2*)g_y)[pix*32 + lane] = acc;   // NHWC, coalesced
    }
}

// ---------------- launch ----------------
extern "C" void kernel_launch(void* const* d_in, const int* in_sizes, int n_in,
                              void* d_out, int out_size) {
    const float* x      = (const float*)d_in[0];
    const float* w_off  = (const float*)d_in[1];
    const float* b_off  = (const float*)d_in[2];
    const float* w_conv = (const float*)d_in[3];
    float* out = (float*)d_out;

    cudaFuncSetAttribute(k_offconv, cudaFuncAttributeMaxDynamicSharedMemorySize,
                         CO_OFF*KIDX*(int)sizeof(float));
    cudaFuncSetAttribute(k_fused, cudaFuncAttributeMaxDynamicSharedMemorySize,
                         KIDX*SWPAD*(int)sizeof(float));

    dim3 tgrid(HW/32, C/32, BB);
    dim3 tblk(32, 8);
    k_transpose_in<<<tgrid, tblk>>>(x);
    k_wtrans<<<(KIDX*C + 1023)/1024, 1024>>>(w_conv);
    k_offconv<<<NPIX/256, 256, CO_OFF*KIDX*sizeof(float)>>>(x, w_off, b_off);
    k_fused<<<1024, 512, KIDX*SWPAD*sizeof(float)>>>();
    k_transpose_out<<<tgrid, tblk>>>(out);
}

// round 2
// speedup vs baseline: 1.9751x; 1.9751x over previous
#include <cuda_runtime.h>
#include <math.h>

#define BB 8
#define C 64
#define H 128
#define W 128
#define HW (H*W)            // 16384
#define NPIX (BB*HW)        // 131072
#define CO_OFF 27
#define KIDX 576            // C*9
#define PGRP 8              // pixels per warp group
#define NGRP (NPIX/PGRP)    // 16384
#define FWARPS 12           // warps per fused block

// ---------------- scratch (no allocations allowed) ----------------
__device__ float g_xT[NPIX*C];           // x in NHWC
__device__ float g_off[BB*CO_OFF*HW];    // offset conv output (b,27,H,W)
__device__ float g_wcT[KIDX*C];          // w_conv transposed [idx][o]
__device__ float g_y[NPIX*C];            // result in NHWC before final transpose

// ---------------- NCHW -> NHWC transpose of x ----------------
__global__ void k_transpose_in(const float* __restrict__ x) {
    __shared__ float tile[32][33];
    int b  = blockIdx.z;
    int c0 = blockIdx.y * 32;
    int p0 = blockIdx.x * 32;
    int tx = threadIdx.x, ty = threadIdx.y;
#pragma unroll
    for (int i = 0; i < 4; i++)
        tile[ty + 8*i][tx] = x[(b*C + c0 + ty + 8*i)*HW + p0 + tx];
    __syncthreads();
#pragma unroll
    for (int i = 0; i < 4; i++)
        g_xT[(b*HW + p0 + ty + 8*i)*C + c0 + tx] = tile[tx][ty + 8*i];
}

// ---------------- NHWC -> NCHW transpose of y ----------------
__global__ void k_transpose_out(float* __restrict__ out) {
    __shared__ float tile[32][33];
    int b  = blockIdx.z;
    int c0 = blockIdx.y * 32;
    int p0 = blockIdx.x * 32;
    int tx = threadIdx.x, ty = threadIdx.y;
#pragma unroll
    for (int i = 0; i < 4; i++)
        tile[ty + 8*i][tx] = g_y[(b*HW + p0 + ty + 8*i)*C + c0 + tx];
    __syncthreads();
#pragma unroll
    for (int i = 0; i < 4; i++)
        out[(b*C + c0 + ty + 8*i)*HW + p0 + tx] = tile[tx][ty + 8*i];
}

// ---------------- transpose w_conv (64,576) -> (576,64) ----------------
__global__ void k_wtrans(const float* __restrict__ w_conv) {
    int i = blockIdx.x * blockDim.x + threadIdx.x;
    if (i < KIDX*C) {
        int o = i & 63, idx = i >> 6;
        g_wcT[i] = w_conv[o*KIDX + idx];
    }
}

// ---------------- offset-predictor 3x3 conv, pad 1 ----------------
// weights in smem as [c*9+t][28] (27 + 1 pad) for float4 loads
__global__ __launch_bounds__(256) void k_offconv(
    const float* __restrict__ x, const float* __restrict__ w_off,
    const float* __restrict__ b_off)
{
    extern __shared__ float sw[];   // [576][28] = 16128 floats
    for (int i = threadIdx.x; i < CO_OFF*KIDX; i += blockDim.x) {
        int co = i / KIDX;
        int r  = i - co*KIDX;
        sw[r*28 + co] = w_off[i];
    }
    __syncthreads();

    int pix = blockIdx.x * blockDim.x + threadIdx.x;
    int b = pix >> 14;
    int h = (pix >> 7) & 127;
    int w = pix & 127;

    // tap offsets + validity (relative to center)
    int   off[9];
    float vmul[9];
#pragma unroll
    for (int t = 0; t < 9; t++) {
        int dy = t/3 - 1, dx = t%3 - 1;
        int yy = h + dy, xx = w + dx;
        bool v = (yy >= 0) && (yy < H) && (xx >= 0) && (xx < W);
        off[t]  = dy*W + dx;
        vmul[t] = v ? 1.f : 0.f;
    }

    float acc[28];
#pragma unroll
    for (int j = 0; j < 27; j++) acc[j] = b_off[j];
    acc[27] = 0.f;

    const float* xc = x + (size_t)b*C*HW + h*W + w;
#pragma unroll 1
    for (int c = 0; c < C; c++) {
        float xv[9];
#pragma unroll
        for (int t = 0; t < 9; t++)
            xv[t] = vmul[t] * __ldg(xc + off[t]);
        const float* wp = sw + c*9*28;
#pragma unroll
        for (int t = 0; t < 9; t++) {
            float xt = xv[t];
#pragma unroll
            for (int j = 0; j < 7; j++) {
                float4 w4 = *(const float4*)(wp + t*28 + 4*j);
                acc[4*j+0] += xt * w4.x;
                acc[4*j+1] += xt * w4.y;
                acc[4*j+2] += xt * w4.z;
                acc[4*j+3] += xt * w4.w;
            }
        }
        xc += HW;
    }
    float* op = g_off + (size_t)b*CO_OFF*HW + h*W + w;
#pragma unroll
    for (int co = 0; co < CO_OFF; co++)
        op[co*HW] = acc[co];
}

// ---------------- fused bilinear sample + mask + 1x1 GEMM ----------------
// one warp handles 8 pixels per group; lanes own channel pair (2l, 2l+1)
__global__ __launch_bounds__(FWARPS*32) void k_fused() {
    extern __shared__ float smem[];
    float* s_w   = smem;                         // [9][64][64] (k,c,o) = 36864
    float* s_v   = smem + 36864;                 // FWARPS * [8][64]    = 6144
    float* s_par = smem + 36864 + FWARPS*512;    // FWARPS * [72][8]    = 6912

    const int tid  = threadIdx.x;
    const int lane = tid & 31;
    const int warp = tid >> 5;

    // stage weights reordered: s_w[(k*64+c)*64 + o] = g_wcT[(c*9+k)*64 + o]
    for (int i = tid; i < KIDX*C; i += blockDim.x) {
        int o = i & 63;
        int srow = i >> 6;         // c*9+k
        int c = srow / 9;
        int k = srow - 9*c;
        s_w[((k*64 + c) << 6) | o] = g_wcT[i];
    }
    __syncthreads();

    float* vbuf = s_v   + warp*512;
    float* par  = s_par + warp*576;
    const int gwarp = blockIdx.x * FWARPS + warp;
    const int nwarp = gridDim.x * FWARPS;
    const float2* xp2 = (const float2*)g_xT;

    for (int g = gwarp; g < NGRP; g += nwarp) {
        const int pixbase = g * PGRP;
        const int b  = pixbase >> 14;
        const int hw = pixbase & 16383;
        const int h  = hw >> 7;
        const int wb = hw & 127;
        const int rb = b * HW;

        // ---- param phase: 72 tasks (k,p) ----
#pragma unroll
        for (int r = 0; r < 3; r++) {
            int t = r*32 + lane;
            if (t < 72) {
                int k = t >> 3, p = t & 7;
                int obase = (b*CO_OFF + k)*HW + hw + p;
                float o1 = g_off[obase];
                float o2 = g_off[obase +  9*HW];
                float mv = g_off[obase + 18*HW];
                float mask = 1.f / (1.f + expf(-mv));
                int kh = k / 3;
                int kw = k - kh*3;
                float px = o1 + (float)(wb + p + kw - 1);
                float py = o2 + (float)(h + kh - 1);
                float x0f = floorf(px), y0f = floorf(py);
                int x0 = (int)x0f, y0 = (int)y0f;
                float wx1 = px - x0f, wy1 = py - y0f;
                float wx0 = 1.f - wx1, wy0 = 1.f - wy1;
                float vx0 = (x0 >= 0  && x0     < W) ? 1.f : 0.f;
                float vx1 = (x0 >= -1 && x0 + 1 < W) ? 1.f : 0.f;
                float vy0 = (y0 >= 0  && y0     < H) ? 1.f : 0.f;
                float vy1 = (y0 >= -1 && y0 + 1 < H) ? 1.f : 0.f;
                int cx0 = min(max(x0,   0), W-1);
                int cx1 = min(max(x0+1, 0), W-1);
                int cy0 = min(max(y0,   0), H-1);
                int cy1 = min(max(y0+1, 0), H-1);
                float4 wt;
                wt.x = wy0*wx0*mask*vy0*vx0;
                wt.y = wy0*wx1*mask*vy0*vx1;
                wt.z = wy1*wx0*mask*vy1*vx0;
                wt.w = wy1*wx1*mask*vy1*vx1;
                float4 fi;
                fi.x = __int_as_float((rb + cy0*W + cx0) << 5);  // float2 index
                fi.y = __int_as_float((rb + cy0*W + cx1) << 5);
                fi.z = __int_as_float((rb + cy1*W + cx0) << 5);
                fi.w = __int_as_float((rb + cy1*W + cx1) << 5);
                *(float4*)(par + t*8)     = wt;
                *(float4*)(par + t*8 + 4) = fi;
            }
        }
        __syncwarp();

        float2 acc[PGRP];
#pragma unroll
        for (int p = 0; p < PGRP; p++) acc[p] = make_float2(0.f, 0.f);

#pragma unroll 1
        for (int k = 0; k < 9; k++) {
            // ---- sample 8 pixels for tap k ----
#pragma unroll
            for (int p = 0; p < PGRP; p++) {
                const float* pp = par + (k*8 + p)*8;
                float4 wt = *(const float4*)(pp);
                float4 fi = *(const float4*)(pp + 4);
                float2 v00 = xp2[__float_as_int(fi.x) + lane];
                float2 v01 = xp2[__float_as_int(fi.y) + lane];
                float2 v10 = xp2[__float_as_int(fi.z) + lane];
                float2 v11 = xp2[__float_as_int(fi.w) + lane];
                float2 v;
                v.x = wt.x*v00.x + wt.y*v01.x + wt.z*v10.x + wt.w*v11.x;
                v.y = wt.x*v00.y + wt.y*v01.y + wt.z*v10.y + wt.w*v11.y;
                *(float2*)(vbuf + p*64 + 2*lane) = v;
            }
            __syncwarp();

            // ---- GEMM slice for tap k: 64 channels in quads ----
            const float* wrow = s_w + (k << 12) + 2*lane;   // (k*64)*64 + 2*lane
#pragma unroll 2
            for (int q = 0; q < 16; q++) {
                const float* wq = wrow + (q << 8);          // 4 rows of 64
                float2 w0 = *(const float2*)(wq);
                float2 w1 = *(const float2*)(wq + 64);
                float2 w2 = *(const float2*)(wq + 128);
                float2 w3 = *(const float2*)(wq + 192);
#pragma unroll
                for (int p = 0; p < PGRP; p++) {
                    float4 v = *(const float4*)(vbuf + p*64 + 4*q);
                    acc[p].x += v.x*w0.x + v.y*w1.x + v.z*w2.x + v.w*w3.x;
                    acc[p].y += v.x*w0.y + v.y*w1.y + v.z*w2.y + v.w*w3.y;
                }
            }
            __syncwarp();
        }

#pragma unroll
        for (int p = 0; p < PGRP; p++)
            *(float2*)(g_y + (size_t)(pixbase + p)*64 + 2*lane) = acc[p];
    }
}

// ---------------- launch ----------------
extern "C" void kernel_launch(void* const* d_in, const int* in_sizes, int n_in,
                              void* d_out, int out_size) {
    const float* x      = (const float*)d_in[0];
    const float* w_off  = (const float*)d_in[1];
    const float* b_off  = (const float*)d_in[2];
    const float* w_conv = (const float*)d_in[3];
    float* out = (float*)d_out;

    const int smem_off   = KIDX*28*(int)sizeof(float);                    // 64512
    const int smem_fused = (36864 + FWARPS*512 + FWARPS*576)*(int)sizeof(float); // 199680

    cudaFuncSetAttribute(k_offconv, cudaFuncAttributeMaxDynamicSharedMemorySize, smem_off);
    cudaFuncSetAttribute(k_fused,   cudaFuncAttributeMaxDynamicSharedMemorySize, smem_fused);

    dim3 tgrid(HW/32, C/32, BB);
    dim3 tblk(32, 8);
    k_transpose_in<<<tgrid, tblk>>>(x);
    k_wtrans<<<(KIDX*C + 1023)/1024, 1024>>>(w_conv);
    k_offconv<<<NPIX/256, 256, smem_off>>>(x, w_off, b_off);
    k_fused<<<152, FWARPS*32, smem_fused>>>();
    k_transpose_out<<<tgrid, tblk>>>(out);
}

// round 4
// speedup vs baseline: 2.1888x; 1.1082x over previous
#include <cuda_runtime.h>
#include <math.h>

#define BB 8
#define C 64
#define H 128
#define W 128
#define HW (H*W)            // 16384
#define NPIX (BB*HW)        // 131072
#define CO_OFF 27
#define KIDX 576            // C*9
#define PGRP 16             // pixels per warp group
#define NGRP (NPIX/PGRP)    // 8192
#define FWARPS 12           // warps per fused block

typedef unsigned long long u64;

// ---------------- packed fp32x2 helpers (sm_103a) ----------------
__device__ __forceinline__ u64 pk(float x, float y) {
    u64 r; asm("mov.b64 %0, {%1, %2};" : "=l"(r) : "f"(x), "f"(y)); return r;
}
__device__ __forceinline__ float2 upk(u64 a) {
    float2 f; asm("mov.b64 {%0, %1}, %2;" : "=f"(f.x), "=f"(f.y) : "l"(a)); return f;
}
__device__ __forceinline__ u64 ffma2(u64 a, u64 b, u64 c) {
    u64 d; asm("fma.rn.f32x2 %0, %1, %2, %3;" : "=l"(d) : "l"(a), "l"(b), "l"(c)); return d;
}
__device__ __forceinline__ u64 fmul2(u64 a, u64 b) {
    u64 d; asm("mul.rn.f32x2 %0, %1, %2;" : "=l"(d) : "l"(a), "l"(b)); return d;
}

// ---------------- scratch (no allocations allowed) ----------------
__device__ float g_xT[NPIX*C];           // x in NHWC
__device__ float g_off[BB*CO_OFF*HW];    // offset conv output (b,27,H,W)
__device__ float g_w2[9*32*64*2];        // weights [k][c2][o][j], c = 2*c2+j
__device__ float g_y[NPIX*C];            // result NHWC

// ---------------- NCHW -> NHWC transpose of x ----------------
__global__ void k_transpose_in(const float* __restrict__ x) {
    __shared__ float tile[32][33];
    int b  = blockIdx.z;
    int c0 = blockIdx.y * 32;
    int p0 = blockIdx.x * 32;
    int tx = threadIdx.x, ty = threadIdx.y;
#pragma unroll
    for (int i = 0; i < 4; i++)
        tile[ty + 8*i][tx] = x[(b*C + c0 + ty + 8*i)*HW + p0 + tx];
    __syncthreads();
#pragma unroll
    for (int i = 0; i < 4; i++)
        g_xT[(b*HW + p0 + ty + 8*i)*C + c0 + tx] = tile[tx][ty + 8*i];
}

// ---------------- NHWC -> NCHW transpose of y ----------------
__global__ void k_transpose_out(float* __restrict__ out) {
    __shared__ float tile[32][33];
    int b  = blockIdx.z;
    int c0 = blockIdx.y * 32;
    int p0 = blockIdx.x * 32;
    int tx = threadIdx.x, ty = threadIdx.y;
#pragma unroll
    for (int i = 0; i < 4; i++)
        tile[ty + 8*i][tx] = g_y[(b*HW + p0 + ty + 8*i)*C + c0 + tx];
    __syncthreads();
#pragma unroll
    for (int i = 0; i < 4; i++)
        out[(b*C + c0 + ty + 8*i)*HW + p0 + tx] = tile[tx][ty + 8*i];
}

// ---------------- reorder w_conv (64,576) -> [k][c2][o][j] ----------------
__global__ void k_wtrans(const float* __restrict__ w_conv) {
    int i = blockIdx.x * blockDim.x + threadIdx.x;
    if (i < 9*32*64*2) {
        int j  = i & 1;
        int o  = (i >> 1) & 63;
        int c2 = (i >> 7) & 31;
        int k  = i >> 12;
        int c  = 2*c2 + j;
        g_w2[i] = w_conv[o*KIDX + c*9 + k];
    }
}

// ---------------- offset-predictor 3x3 conv, pad 1, 2 px/thread ----------------
__global__ __launch_bounds__(256) void k_offconv(
    const float* __restrict__ x, const float* __restrict__ w_off,
    const float* __restrict__ b_off)
{
    extern __shared__ float sw[];   // [576][28]
    for (int i = threadIdx.x; i < CO_OFF*KIDX; i += blockDim.x) {
        int co = i / KIDX;
        int r  = i - co*KIDX;
        sw[r*28 + co] = w_off[i];
    }
    __syncthreads();

    int pix0 = blockIdx.x * 512 + threadIdx.x;   // second pixel: +256 (=+2 rows)
    int b  = pix0 >> 14;
    int h0 = (pix0 >> 7) & 127;
    int w0 = pix0 & 127;
    int h1 = h0 + 2;

    int   off[9];
    float vm0[9], vm1[9];
#pragma unroll
    for (int t = 0; t < 9; t++) {
        int dy = t/3 - 1, dx = t%3 - 1;
        off[t] = dy*W + dx;
        int xx = w0 + dx;
        bool vx = (xx >= 0) && (xx < W);
        int y0 = h0 + dy, y1 = h1 + dy;
        vm0[t] = (vx && y0 >= 0 && y0 < H) ? 1.f : 0.f;
        vm1[t] = (vx && y1 >= 0 && y1 < H) ? 1.f : 0.f;
    }

    u64 acc0[14], acc1[14];
#pragma unroll
    for (int j = 0; j < 13; j++) { acc0[j] = pk(b_off[2*j], b_off[2*j+1]); acc1[j] = acc0[j]; }
    acc0[13] = pk(b_off[26], 0.f); acc1[13] = acc0[13];

    const float* xc0 = x + (size_t)b*C*HW + h0*W + w0;
    const float* xc1 = xc0 + 2*W;
#pragma unroll 1
    for (int c = 0; c < C; c++) {
        float xv0[9], xv1[9];
#pragma unroll
        for (int t = 0; t < 9; t++) {
            xv0[t] = vm0[t] * __ldg(xc0 + off[t]);
            xv1[t] = vm1[t] * __ldg(xc1 + off[t]);
        }
        const float* wp = sw + c*9*28;
#pragma unroll
        for (int t = 0; t < 9; t++) {
            u64 s0 = pk(xv0[t], xv0[t]);
            u64 s1 = pk(xv1[t], xv1[t]);
#pragma unroll
            for (int j = 0; j < 7; j++) {
                float4 w4 = *(const float4*)(wp + t*28 + 4*j);
                u64 wA = pk(w4.x, w4.y);
                u64 wB = pk(w4.z, w4.w);
                acc0[2*j]   = ffma2(s0, wA, acc0[2*j]);
                acc0[2*j+1] = ffma2(s0, wB, acc0[2*j+1]);
                acc1[2*j]   = ffma2(s1, wA, acc1[2*j]);
                acc1[2*j+1] = ffma2(s1, wB, acc1[2*j+1]);
            }
        }
        xc0 += HW; xc1 += HW;
    }
    float* op0 = g_off + (size_t)b*CO_OFF*HW + h0*W + w0;
    float* op1 = op0 + 2*W;
#pragma unroll
    for (int j = 0; j < 13; j++) {
        float2 a = upk(acc0[j]); float2 bq = upk(acc1[j]);
        op0[(2*j)*HW] = a.x;  op0[(2*j+1)*HW] = a.y;
        op1[(2*j)*HW] = bq.x; op1[(2*j+1)*HW] = bq.y;
    }
    op0[26*HW] = upk(acc0[13]).x;
    op1[26*HW] = upk(acc1[13]).x;
}

// ---------------- fused bilinear sample + mask + 1x1 GEMM ----------------
// one warp handles 16 pixels/group; lanes own channel pair (2l, 2l+1);
// packed-f32x2 accumulation over (even c, odd c) partial sums
__global__ __launch_bounds__(FWARPS*32, 1) void k_fused() {
    extern __shared__ float smem[];
    float* s_w   = smem;                          // [9][32][64][2] = 36864
    float* s_v   = smem + 36864;                  // FWARPS * [16][64] = 12288
    float* s_par = s_v + FWARPS*1024;             // FWARPS * [32][8]  = 3072

    const int tid  = threadIdx.x;
    const int lane = tid & 31;
    const int warp = tid >> 5;

    // stage weights (already reordered in g_w2): straight float4 copy
    {
        const float4* src = (const float4*)g_w2;
        float4* dst = (float4*)s_w;
        for (int i = tid; i < 9*32*64*2/4; i += blockDim.x)
            dst[i] = src[i];
    }
    __syncthreads();

    float* vbuf = s_v   + warp*1024;
    float* par  = s_par + warp*256;
    const int gwarp = blockIdx.x * FWARPS + warp;
    const int nwarp = gridDim.x * FWARPS;
    const float2* xp2 = (const float2*)g_xT;

    for (int g = gwarp; g < NGRP; g += nwarp) {
        const int pixbase = g * PGRP;             // 16 px, same row
        const int b  = pixbase >> 14;
        const int hw = pixbase & 16383;
        const int h  = hw >> 7;
        const int wb = hw & 127;
        const int rb = b * HW;

        u64 accA[PGRP], accB[PGRP];
#pragma unroll
        for (int p = 0; p < PGRP; p++) { accA[p] = 0ull; accB[p] = 0ull; }

#pragma unroll 1
        for (int k0 = 0; k0 < 9; k0 += 2) {
            // ---- params for taps k0, k0+1 (32 tasks = 1 round) ----
            {
                int t = lane;
                int k = k0 + (t >> 4);
                int p = t & 15;
                if (k < 9) {
                    int obase = (b*CO_OFF + k)*HW + hw + p;
                    float o1 = g_off[obase];
                    float o2 = g_off[obase +  9*HW];
                    float mv = g_off[obase + 18*HW];
                    float mask = 1.f / (1.f + expf(-mv));
                    int kh = k / 3;
                    int kw = k - kh*3;
                    float px = o1 + (float)(wb + p + kw - 1);
                    float py = o2 + (float)(h + kh - 1);
                    float x0f = floorf(px), y0f = floorf(py);
                    int x0 = (int)x0f, y0 = (int)y0f;
                    float wx1 = px - x0f, wy1 = py - y0f;
                    float wx0 = 1.f - wx1, wy0 = 1.f - wy1;
                    float vx0 = (x0 >= 0  && x0     < W) ? 1.f : 0.f;
                    float vx1 = (x0 >= -1 && x0 + 1 < W) ? 1.f : 0.f;
                    float vy0 = (y0 >= 0  && y0     < H) ? 1.f : 0.f;
                    float vy1 = (y0 >= -1 && y0 + 1 < H) ? 1.f : 0.f;
                    int cx0 = min(max(x0,   0), W-1);
                    int cx1 = min(max(x0+1, 0), W-1);
                    int cy0 = min(max(y0,   0), H-1);
                    int cy1 = min(max(y0+1, 0), H-1);
                    float4 wt;
                    wt.x = wy0*wx0*mask*vy0*vx0;
                    wt.y = wy0*wx1*mask*vy0*vx1;
                    wt.z = wy1*wx0*mask*vy1*vx0;
                    wt.w = wy1*wx1*mask*vy1*vx1;
                    float4 fi;
                    fi.x = __int_as_float((rb + cy0*W + cx0) << 5);  // float2 index
                    fi.y = __int_as_float((rb + cy0*W + cx1) << 5);
                    fi.z = __int_as_float((rb + cy1*W + cx0) << 5);
                    fi.w = __int_as_float((rb + cy1*W + cx1) << 5);
                    *(float4*)(par + t*8)     = wt;
                    *(float4*)(par + t*8 + 4) = fi;
                }
            }
            __syncwarp();

#pragma unroll
            for (int kk = 0; kk < 2; kk++) {
                int k = k0 + kk;
                if (k > 8) break;

                // ---- sample 16 pixels for tap k ----
#pragma unroll
                for (int p = 0; p < PGRP; p++) {
                    const float* pp = par + (kk*16 + p)*8;
                    float4 wt = *(const float4*)(pp);
                    float4 fi = *(const float4*)(pp + 4);
                    float2 v00 = xp2[__float_as_int(fi.x) + lane];
                    float2 v01 = xp2[__float_as_int(fi.y) + lane];
                    float2 v10 = xp2[__float_as_int(fi.z) + lane];
                    float2 v11 = xp2[__float_as_int(fi.w) + lane];
                    u64 r = fmul2(pk(wt.x, wt.x), pk(v00.x, v00.y));
                    r = ffma2(pk(wt.y, wt.y), pk(v01.x, v01.y), r);
                    r = ffma2(pk(wt.z, wt.z), pk(v10.x, v10.y), r);
                    r = ffma2(pk(wt.w, wt.w), pk(v11.x, v11.y), r);
                    *(float2*)(vbuf + p*64 + 2*lane) = upk(r);
                }
                __syncwarp();

                // ---- GEMM slice for tap k: 32 c-pairs (q = 0..15) ----
                const float* wk = s_w + (k << 12) + 4*lane;   // k*32*128 + o*2
#pragma unroll 4
                for (int q = 0; q < 16; q++) {
                    float4 w0 = *(const float4*)(wk + (2*q)*128);     // c = 4q, 4q+1
                    float4 w1 = *(const float4*)(wk + (2*q+1)*128);   // c = 4q+2, 4q+3
                    u64 w0A = pk(w0.x, w0.y), w0B = pk(w0.z, w0.w);
                    u64 w1A = pk(w1.x, w1.y), w1B = pk(w1.z, w1.w);
#pragma unroll
                    for (int p = 0; p < PGRP; p++) {
                        float4 v4 = *(const float4*)(vbuf + p*64 + 4*q);
                        u64 vP0 = pk(v4.x, v4.y);
                        u64 vP1 = pk(v4.z, v4.w);
                        accA[p] = ffma2(vP0, w0A, accA[p]);
                        accB[p] = ffma2(vP0, w0B, accB[p]);
                        accA[p] = ffma2(vP1, w1A, accA[p]);
                        accB[p] = ffma2(vP1, w1B, accB[p]);
                    }
                }
                __syncwarp();
            }
        }

#pragma unroll
        for (int p = 0; p < PGRP; p++) {
            float2 a = upk(accA[p]);
            float2 c = upk(accB[p]);
            float2 o = make_float2(a.x + a.y, c.x + c.y);
            *(float2*)(g_y + (size_t)(pixbase + p)*64 + 2*lane) = o;
        }
    }
}

// ---------------- launch ----------------
extern "C" void kernel_launch(void* const* d_in, const int* in_sizes, int n_in,
                              void* d_out, int out_size) {
    const float* x      = (const float*)d_in[0];
    const float* w_off  = (const float*)d_in[1];
    const float* b_off  = (const float*)d_in[2];
    const float* w_conv = (const float*)d_in[3];
    float* out = (float*)d_out;

    const int smem_off   = KIDX*28*(int)sizeof(float);                      // 64512
    const int smem_fused = (36864 + FWARPS*1024 + FWARPS*256)*(int)sizeof(float); // 208896

    cudaFuncSetAttribute(k_offconv, cudaFuncAttributeMaxDynamicSharedMemorySize, smem_off);
    cudaFuncSetAttribute(k_fused,   cudaFuncAttributeMaxDynamicSharedMemorySize, smem_fused);

    dim3 tgrid(HW/32, C/32, BB);
    dim3 tblk(32, 8);
    k_transpose_in<<<tgrid, tblk>>>(x);
    k_wtrans<<<(9*32*64*2 + 1023)/1024, 1024>>>(w_conv);
    k_offconv<<<NPIX/512, 256, smem_off>>>(x, w_off, b_off);
    k_fused<<<152, FWARPS*32, smem_fused>>>();
    k_transpose_out<<<tgrid, tblk>>>(out);
}

// round 5
// speedup vs baseline: 2.3085x; 1.0547x over previous
#include <cuda_runtime.h>
#include <math.h>

#define BB 8
#define C 64
#define H 128
#define W 128
#define HW (H*W)            // 16384
#define NPIX (BB*HW)        // 131072
#define CO_OFF 27
#define KIDX 576            // C*9
#define PGRP 8              // pixels per warp group
#define NGRP (NPIX/PGRP)    // 16384
#define FWARPS 14           // warps per fused block

typedef unsigned long long u64;

// ---------------- packed fp32x2 helpers (sm_103a) ----------------
__device__ __forceinline__ u64 pk(float x, float y) {
    u64 r; asm("mov.b64 %0, {%1, %2};" : "=l"(r) : "f"(x), "f"(y)); return r;
}
__device__ __forceinline__ float2 upk(u64 a) {
    float2 f; asm("mov.b64 {%0, %1}, %2;" : "=f"(f.x), "=f"(f.y) : "l"(a)); return f;
}
__device__ __forceinline__ u64 ffma2(u64 a, u64 b, u64 c) {
    u64 d; asm("fma.rn.f32x2 %0, %1, %2, %3;" : "=l"(d) : "l"(a), "l"(b), "l"(c)); return d;
}
__device__ __forceinline__ u64 fmul2(u64 a, u64 b) {
    u64 d; asm("mul.rn.f32x2 %0, %1, %2;" : "=l"(d) : "l"(a), "l"(b)); return d;
}

// ---------------- scratch (no allocations allowed) ----------------
__device__ float g_xT[NPIX*C];           // x in NHWC
__device__ float g_off[BB*CO_OFF*HW];    // offset conv output (b,27,H,W)
__device__ float g_w2[9*32*64*2];        // weights [k][c2][o][j], c = 2*c2+j
__device__ float g_y[NPIX*C];            // result NHWC

// ---------------- NCHW -> NHWC transpose of x ----------------
__global__ void k_transpose_in(const float* __restrict__ x) {
    __shared__ float tile[32][33];
    int b  = blockIdx.z;
    int c0 = blockIdx.y * 32;
    int p0 = blockIdx.x * 32;
    int tx = threadIdx.x, ty = threadIdx.y;
#pragma unroll
    for (int i = 0; i < 4; i++)
        tile[ty + 8*i][tx] = x[(b*C + c0 + ty + 8*i)*HW + p0 + tx];
    __syncthreads();
#pragma unroll
    for (int i = 0; i < 4; i++)
        g_xT[(b*HW + p0 + ty + 8*i)*C + c0 + tx] = tile[tx][ty + 8*i];
}

// ---------------- NHWC -> NCHW transpose of y ----------------
__global__ void k_transpose_out(float* __restrict__ out) {
    __shared__ float tile[32][33];
    int b  = blockIdx.z;
    int c0 = blockIdx.y * 32;
    int p0 = blockIdx.x * 32;
    int tx = threadIdx.x, ty = threadIdx.y;
#pragma unroll
    for (int i = 0; i < 4; i++)
        tile[ty + 8*i][tx] = g_y[(b*HW + p0 + ty + 8*i)*C + c0 + tx];
    __syncthreads();
#pragma unroll
    for (int i = 0; i < 4; i++)
        out[(b*C + c0 + ty + 8*i)*HW + p0 + tx] = tile[tx][ty + 8*i];
}

// ---------------- reorder w_conv (64,576) -> [k][c2][o][j] ----------------
__global__ void k_wtrans(const float* __restrict__ w_conv) {
    int i = blockIdx.x * blockDim.x + threadIdx.x;
    if (i < 9*32*64*2) {
        int j  = i & 1;
        int o  = (i >> 1) & 63;
        int c2 = (i >> 7) & 31;
        int k  = i >> 12;
        int c  = 2*c2 + j;
        g_w2[i] = w_conv[o*KIDX + c*9 + k];
    }
}

// ---------------- offset-predictor 3x3 conv, pad 1, 2 px/thread ----------------
__global__ __launch_bounds__(256) void k_offconv(
    const float* __restrict__ x, const float* __restrict__ w_off,
    const float* __restrict__ b_off)
{
    extern __shared__ float sw[];   // [576][28]
    for (int i = threadIdx.x; i < CO_OFF*KIDX; i += blockDim.x) {
        int co = i / KIDX;
        int r  = i - co*KIDX;
        sw[r*28 + co] = w_off[i];
    }
    __syncthreads();

    int pix0 = blockIdx.x * 512 + threadIdx.x;   // second pixel: +256 (=+2 rows)
    int b  = pix0 >> 14;
    int h0 = (pix0 >> 7) & 127;
    int w0 = pix0 & 127;
    int h1 = h0 + 2;

    int   off[9];
    float vm0[9], vm1[9];
#pragma unroll
    for (int t = 0; t < 9; t++) {
        int dy = t/3 - 1, dx = t%3 - 1;
        off[t] = dy*W + dx;
        int xx = w0 + dx;
        bool vx = (xx >= 0) && (xx < W);
        int y0 = h0 + dy, y1 = h1 + dy;
        vm0[t] = (vx && y0 >= 0 && y0 < H) ? 1.f : 0.f;
        vm1[t] = (vx && y1 >= 0 && y1 < H) ? 1.f : 0.f;
    }

    u64 acc0[14], acc1[14];
#pragma unroll
    for (int j = 0; j < 13; j++) { acc0[j] = pk(b_off[2*j], b_off[2*j+1]); acc1[j] = acc0[j]; }
    acc0[13] = pk(b_off[26], 0.f); acc1[13] = acc0[13];

    const float* xc0 = x + (size_t)b*C*HW + h0*W + w0;
    const float* xc1 = xc0 + 2*W;
#pragma unroll 1
    for (int c = 0; c < C; c++) {
        float xv0[9], xv1[9];
#pragma unroll
        for (int t = 0; t < 9; t++) {
            xv0[t] = vm0[t] * __ldg(xc0 + off[t]);
            xv1[t] = vm1[t] * __ldg(xc1 + off[t]);
        }
        const float* wp = sw + c*9*28;
#pragma unroll
        for (int t = 0; t < 9; t++) {
            u64 s0 = pk(xv0[t], xv0[t]);
            u64 s1 = pk(xv1[t], xv1[t]);
#pragma unroll
            for (int j = 0; j < 7; j++) {
                float4 w4 = *(const float4*)(wp + t*28 + 4*j);
                u64 wA = pk(w4.x, w4.y);
                u64 wB = pk(w4.z, w4.w);
                acc0[2*j]   = ffma2(s0, wA, acc0[2*j]);
                acc0[2*j+1] = ffma2(s0, wB, acc0[2*j+1]);
                acc1[2*j]   = ffma2(s1, wA, acc1[2*j]);
                acc1[2*j+1] = ffma2(s1, wB, acc1[2*j+1]);
            }
        }
        xc0 += HW; xc1 += HW;
    }
    float* op0 = g_off + (size_t)b*CO_OFF*HW + h0*W + w0;
    float* op1 = op0 + 2*W;
#pragma unroll
    for (int j = 0; j < 13; j++) {
        float2 a = upk(acc0[j]); float2 bq = upk(acc1[j]);
        op0[(2*j)*HW] = a.x;  op0[(2*j+1)*HW] = a.y;
        op1[(2*j)*HW] = bq.x; op1[(2*j+1)*HW] = bq.y;
    }
    op0[26*HW] = upk(acc0[13]).x;
    op1[26*HW] = upk(acc1[13]).x;
}

// ---------------- fused bilinear sample + mask + 1x1 GEMM ----------------
// one warp handles 8 pixels/group; software pipeline: gathers for tap k+1
// issued before GEMM of tap k, so L2 latency is hidden under FFMA2 work.
__global__ __launch_bounds__(FWARPS*32, 1) void k_fused() {
    extern __shared__ float smem[];
    float* s_w   = smem;                          // [9][32][64][2] = 36864
    float* s_v   = smem + 36864;                  // FWARPS * [8][64]  = 7168
    float* s_par = s_v + FWARPS*512;              // FWARPS * [72][8]  = 8064

    const int tid  = threadIdx.x;
    const int lane = tid & 31;
    const int warp = tid >> 5;

    // stage weights (already reordered in g_w2): straight float4 copy
    {
        const float4* src = (const float4*)g_w2;
        float4* dst = (float4*)s_w;
        for (int i = tid; i < 9*32*64*2/4; i += blockDim.x)
            dst[i] = src[i];
    }
    __syncthreads();

    float* vbuf = s_v   + warp*512;
    float* par  = s_par + warp*576;
    const int gwarp = blockIdx.x * FWARPS + warp;
    const int nwarp = gridDim.x * FWARPS;
    const float2* xp2 = (const float2*)g_xT;

    for (int g = gwarp; g < NGRP; g += nwarp) {
        const int pixbase = g * PGRP;             // 8 px, same row
        const int b  = pixbase >> 14;
        const int hw = pixbase & 16383;
        const int h  = hw >> 7;
        const int wb = hw & 127;
        const int rb = b * HW;

        // ---- params for all 9 taps x 8 px = 72 tasks ----
#pragma unroll
        for (int r = 0; r < 3; r++) {
            int t = r*32 + lane;
            if (t < 72) {
                int k = t >> 3, p = t & 7;
                int obase = (b*CO_OFF + k)*HW + hw + p;
                float o1 = g_off[obase];
                float o2 = g_off[obase +  9*HW];
                float mv = g_off[obase + 18*HW];
                float mask = 1.f / (1.f + expf(-mv));
                int kh = k / 3;
                int kw = k - kh*3;
                float px = o1 + (float)(wb + p + kw - 1);
                float py = o2 + (float)(h + kh - 1);
                float x0f = floorf(px), y0f = floorf(py);
                int x0 = (int)x0f, y0 = (int)y0f;
                float wx1 = px - x0f, wy1 = py - y0f;
                float wx0 = 1.f - wx1, wy0 = 1.f - wy1;
                float vx0 = (x0 >= 0  && x0     < W) ? 1.f : 0.f;
                float vx1 = (x0 >= -1 && x0 + 1 < W) ? 1.f : 0.f;
                float vy0 = (y0 >= 0  && y0     < H) ? 1.f : 0.f;
                float vy1 = (y0 >= -1 && y0 + 1 < H) ? 1.f : 0.f;
                int cx0 = min(max(x0,   0), W-1);
                int cx1 = min(max(x0+1, 0), W-1);
                int cy0 = min(max(y0,   0), H-1);
                int cy1 = min(max(y0+1, 0), H-1);
                float4 wt;
                wt.x = wy0*wx0*mask*vy0*vx0;
                wt.y = wy0*wx1*mask*vy0*vx1;
                wt.z = wy1*wx0*mask*vy1*vx0;
                wt.w = wy1*wx1*mask*vy1*vx1;
                float4 fi;
                fi.x = __int_as_float((rb + cy0*W + cx0) << 5);  // float2 index
                fi.y = __int_as_float((rb + cy0*W + cx1) << 5);
                fi.z = __int_as_float((rb + cy1*W + cx0) << 5);
                fi.w = __int_as_float((rb + cy1*W + cx1) << 5);
                *(float4*)(par + t*8)     = wt;
                *(float4*)(par + t*8 + 4) = fi;
            }
        }
        __syncwarp();

        u64 accA[PGRP], accB[PGRP];
#pragma unroll
        for (int p = 0; p < PGRP; p++) { accA[p] = 0ull; accB[p] = 0ull; }

        // prefetch registers: 4 corners x 8 px
        float2 c00[PGRP], c01[PGRP], c10[PGRP], c11[PGRP];

        // prologue: gather + combine tap 0
#pragma unroll
        for (int p = 0; p < PGRP; p++) {
            float4 fi = *(const float4*)(par + p*8 + 4);
            c00[p] = xp2[__float_as_int(fi.x) + lane];
            c01[p] = xp2[__float_as_int(fi.y) + lane];
            c10[p] = xp2[__float_as_int(fi.z) + lane];
            c11[p] = xp2[__float_as_int(fi.w) + lane];
        }
#pragma unroll
        for (int p = 0; p < PGRP; p++) {
            float4 wt = *(const float4*)(par + p*8);
            u64 r = fmul2(pk(wt.x, wt.x), pk(c00[p].x, c00[p].y));
            r = ffma2(pk(wt.y, wt.y), pk(c01[p].x, c01[p].y), r);
            r = ffma2(pk(wt.z, wt.z), pk(c10[p].x, c10[p].y), r);
            r = ffma2(pk(wt.w, wt.w), pk(c11[p].x, c11[p].y), r);
            *(float2*)(vbuf + p*64 + 2*lane) = upk(r);
        }
        __syncwarp();

#pragma unroll 1
        for (int k = 0; k < 9; k++) {
            // ---- issue gathers for tap k+1 (in flight during GEMM) ----
            if (k < 8) {
                const float* pn = par + (k+1)*64;
#pragma unroll
                for (int p = 0; p < PGRP; p++) {
                    float4 fi = *(const float4*)(pn + p*8 + 4);
                    c00[p] = xp2[__float_as_int(fi.x) + lane];
                    c01[p] = xp2[__float_as_int(fi.y) + lane];
                    c10[p] = xp2[__float_as_int(fi.z) + lane];
                    c11[p] = xp2[__float_as_int(fi.w) + lane];
                }
            }

            // ---- GEMM slice for tap k: 32 c-pairs ----
            const float* wk = s_w + (k << 12) + 4*lane;   // k*32*128 + o*2
#pragma unroll 2
            for (int q = 0; q < 16; q++) {
                float4 w0 = *(const float4*)(wk + (2*q)*128);     // c = 4q, 4q+1
                float4 w1 = *(const float4*)(wk + (2*q+1)*128);   // c = 4q+2, 4q+3
                u64 w0A = pk(w0.x, w0.y), w0B = pk(w0.z, w0.w);
                u64 w1A = pk(w1.x, w1.y), w1B = pk(w1.z, w1.w);
#pragma unroll
                for (int p = 0; p < PGRP; p++) {
                    float4 v4 = *(const float4*)(vbuf + p*64 + 4*q);
                    u64 vP0 = pk(v4.x, v4.y);
                    u64 vP1 = pk(v4.z, v4.w);
                    accA[p] = ffma2(vP0, w0A, accA[p]);
                    accB[p] = ffma2(vP0, w0B, accB[p]);
                    accA[p] = ffma2(vP1, w1A, accA[p]);
                    accB[p] = ffma2(vP1, w1B, accB[p]);
                }
            }
            __syncwarp();   // GEMM done reading vbuf

            // ---- combine prefetched corners -> vbuf for tap k+1 ----
            if (k < 8) {
                const float* pn = par + (k+1)*64;
#pragma unroll
                for (int p = 0; p < PGRP; p++) {
                    float4 wt = *(const float4*)(pn + p*8);
                    u64 r = fmul2(pk(wt.x, wt.x), pk(c00[p].x, c00[p].y));
                    r = ffma2(pk(wt.y, wt.y), pk(c01[p].x, c01[p].y), r);
                    r = ffma2(pk(wt.z, wt.z), pk(c10[p].x, c10[p].y), r);
                    r = ffma2(pk(wt.w, wt.w), pk(c11[p].x, c11[p].y), r);
                    *(float2*)(vbuf + p*64 + 2*lane) = upk(r);
                }
                __syncwarp();
            }
        }

#pragma unroll
        for (int p = 0; p < PGRP; p++) {
            float2 a = upk(accA[p]);
            float2 c = upk(accB[p]);
            float2 o = make_float2(a.x + a.y, c.x + c.y);
            *(float2*)(g_y + (size_t)(pixbase + p)*64 + 2*lane) = o;
        }
    }
}

// ---------------- launch ----------------
extern "C" void kernel_launch(void* const* d_in, const int* in_sizes, int n_in,
                              void* d_out, int out_size) {
    const float* x      = (const float*)d_in[0];
    const float* w_off  = (const float*)d_in[1];
    const float* b_off  = (const float*)d_in[2];
    const float* w_conv = (const float*)d_in[3];
    float* out = (float*)d_out;

    const int smem_off   = KIDX*28*(int)sizeof(float);                        // 64512
    const int smem_fused = (36864 + FWARPS*512 + FWARPS*576)*(int)sizeof(float); // 208384

    cudaFuncSetAttribute(k_offconv, cudaFuncAttributeMaxDynamicSharedMemorySize, smem_off);
    cudaFuncSetAttribute(k_fused,   cudaFuncAttributeMaxDynamicSharedMemorySize, smem_fused);

    dim3 tgrid(HW/32, C/32, BB);
    dim3 tblk(32, 8);
    k_transpose_in<<<tgrid, tblk>>>(x);
    k_wtrans<<<(9*32*64*2 + 1023)/1024, 1024>>>(w_conv);
    k_offconv<<<NPIX/512, 256, smem_off>>>(x, w_off, b_off);
    k_fused<<<152, FWARPS*32, smem_fused>>>();
    k_transpose_out<<<tgrid, tblk>>>(out);
}

// round 7
// speedup vs baseline: 3.2890x; 1.4247x over previous
#include <cuda_runtime.h>
#include <cuda_bf16.h>
#include <math.h>

#define BB 8
#define C 64
#define H 128
#define W 128
#define HW (H*W)            // 16384
#define NPIX (BB*HW)        // 131072
#define CO_OFF 27
#define KIDX 576
#define NTILE 1024          // 128 px per tile (one image row)

typedef unsigned long long u64;

// ---------------- packed fp32x2 helpers ----------------
__device__ __forceinline__ u64 pk(float x, float y) {
    u64 r; asm("mov.b64 %0, {%1, %2};" : "=l"(r) : "f"(x), "f"(y)); return r;
}
__device__ __forceinline__ float2 upk(u64 a) {
    float2 f; asm("mov.b64 {%0, %1}, %2;" : "=f"(f.x), "=f"(f.y) : "l"(a)); return f;
}
__device__ __forceinline__ u64 ffma2(u64 a, u64 b, u64 c) {
    u64 d; asm("fma.rn.f32x2 %0, %1, %2, %3;" : "=l"(d) : "l"(a), "l"(b), "l"(c)); return d;
}
__device__ __forceinline__ u64 fmul2(u64 a, u64 b) {
    u64 d; asm("mul.rn.f32x2 %0, %1, %2;" : "=l"(d) : "l"(a), "l"(b)); return d;
}
// bf16x2 pack: x -> low half, y -> high half
__device__ __forceinline__ unsigned bf16x2_of(float x, float y) {
    unsigned r; asm("cvt.rn.satfinite.bf16x2.f32 %0, %1, %2;" : "=r"(r) : "f"(y), "f"(x)); return r;
}

// ---------------- mma.sync / ldmatrix (baseline PTX, compiles on compute_103) ----
__device__ __forceinline__ void ldsm_x4(unsigned& r0, unsigned& r1, unsigned& r2, unsigned& r3,
                                        unsigned addr) {
    asm volatile("ldmatrix.sync.aligned.m8n8.x4.shared.b16 {%0,%1,%2,%3}, [%4];"
        : "=r"(r0), "=r"(r1), "=r"(r2), "=r"(r3) : "r"(addr));
}
__device__ __forceinline__ void ldsm_x4t(unsigned& r0, unsigned& r1, unsigned& r2, unsigned& r3,
                                         unsigned addr) {
    asm volatile("ldmatrix.sync.aligned.m8n8.x4.trans.shared.b16 {%0,%1,%2,%3}, [%4];"
        : "=r"(r0), "=r"(r1), "=r"(r2), "=r"(r3) : "r"(addr));
}
__device__ __forceinline__ void mma16816(float* c,
                                         unsigned a0, unsigned a1, unsigned a2, unsigned a3,
                                         unsigned b0, unsigned b1) {
    asm volatile(
        "mma.sync.aligned.m16n8k16.row.col.f32.bf16.bf16.f32 "
        "{%0,%1,%2,%3}, {%4,%5,%6,%7}, {%8,%9}, {%0,%1,%2,%3};"
        : "+f"(c[0]), "+f"(c[1]), "+f"(c[2]), "+f"(c[3])
        : "r"(a0), "r"(a1), "r"(a2), "r"(a3), "r"(b0), "r"(b1));
}
__device__ __forceinline__ unsigned smem_u32(const void* p) {
    unsigned a; asm("{ .reg .u64 t; cvta.to.shared.u64 t, %1; cvt.u32.u64 %0, t; }" : "=r"(a) : "l"(p));
    return a;
}

// ---------------- scratch ----------------
__device__ float g_xT[NPIX*C];                            // x NHWC
__device__ float g_off[BB*CO_OFF*HW];                     // offset conv out
__device__ __align__(16) unsigned short g_wB[9*2*64*64];  // W hi/lo, ldmatrix-ready blocks
__device__ float g_y[NPIX*C];                             // result NHWC

// ---------------- NCHW -> NHWC transpose of x ----------------
__global__ void k_transpose_in(const float* __restrict__ x) {
    __shared__ float tile[32][33];
    int b  = blockIdx.z;
    int c0 = blockIdx.y * 32;
    int p0 = blockIdx.x * 32;
    int tx = threadIdx.x, ty = threadIdx.y;
#pragma unroll
    for (int i = 0; i < 4; i++)
        tile[ty + 8*i][tx] = x[(b*C + c0 + ty + 8*i)*HW + p0 + tx];
    __syncthreads();
#pragma unroll
    for (int i = 0; i < 4; i++)
        g_xT[(b*HW + p0 + ty + 8*i)*C + c0 + tx] = tile[tx][ty + 8*i];
}

// ---------------- NHWC -> NCHW transpose of y ----------------
__global__ void k_transpose_out(float* __restrict__ out) {
    __shared__ float tile[32][33];
    int b  = blockIdx.z;
    int c0 = blockIdx.y * 32;
    int p0 = blockIdx.x * 32;
    int tx = threadIdx.x, ty = threadIdx.y;
#pragma unroll
    for (int i = 0; i < 4; i++)
        tile[ty + 8*i][tx] = g_y[(b*HW + p0 + ty + 8*i)*C + c0 + tx];
    __syncthreads();
#pragma unroll
    for (int i = 0; i < 4; i++)
        out[(b*C + c0 + ty + 8*i)*HW + p0 + tx] = tile[tx][ty + 8*i];
}

// ---------------- prep: W -> bf16 hi/lo ldmatrix blocks ----------------
// block(k, hl, kc, n16) = 512B: [16 ch rows][16 o cols] bf16, XOR-swizzled
__global__ void k_wprep(const float* __restrict__ w_conv) {
    int i = blockIdx.x * blockDim.x + threadIdx.x;
    if (i >= 9*2*64*64) return;
    int o  = i & 63;
    int ch = (i >> 6) & 63;
    int hl = (i >> 12) & 1;
    int k  = i >> 13;
    float w = w_conv[o*KIDX + ch*9 + k];
    __nv_bfloat16 hi = __float2bfloat16(w);
    unsigned short val;
    if (hl == 0) {
        val = *(unsigned short*)&hi;
    } else {
        float fhi = __bfloat162float(hi);
        __nv_bfloat16 lo = __float2bfloat16(w - fhi);
        val = *(unsigned short*)&lo;
    }
    unsigned block = (unsigned)(((k*2 + hl)*16) + (ch >> 4)*4 + (o >> 4));
    unsigned inner = (unsigned)((ch & 15)*32 + (o & 15)*2);
    inner ^= ((inner >> 7) & 1) << 4;
    *(unsigned short*)((char*)g_wB + block*512 + inner) = val;
}

// ---------------- offset-predictor 3x3 conv, pad 1, 2 px/thread ----------------
__global__ __launch_bounds__(256) void k_offconv(
    const float* __restrict__ x, const float* __restrict__ w_off,
    const float* __restrict__ b_off)
{
    extern __shared__ float sw[];   // [576][28]
    for (int i = threadIdx.x; i < CO_OFF*KIDX; i += blockDim.x) {
        int co = i / KIDX;
        int r  = i - co*KIDX;
        sw[r*28 + co] = w_off[i];
    }
    __syncthreads();

    int pix0 = blockIdx.x * 512 + threadIdx.x;
    int b  = pix0 >> 14;
    int h0 = (pix0 >> 7) & 127;
    int w0 = pix0 & 127;
    int h1 = h0 + 2;

    int   off[9];
    float vm0[9], vm1[9];
#pragma unroll
    for (int t = 0; t < 9; t++) {
        int dy = t/3 - 1, dx = t%3 - 1;
        off[t] = dy*W + dx;
        int xx = w0 + dx;
        bool vx = (xx >= 0) && (xx < W);
        int y0 = h0 + dy, y1 = h1 + dy;
        vm0[t] = (vx && y0 >= 0 && y0 < H) ? 1.f : 0.f;
        vm1[t] = (vx && y1 >= 0 && y1 < H) ? 1.f : 0.f;
    }

    u64 acc0[14], acc1[14];
#pragma unroll
    for (int j = 0; j < 13; j++) { acc0[j] = pk(b_off[2*j], b_off[2*j+1]); acc1[j] = acc0[j]; }
    acc0[13] = pk(b_off[26], 0.f); acc1[13] = acc0[13];

    const float* xc0 = x + (size_t)b*C*HW + h0*W + w0;
    const float* xc1 = xc0 + 2*W;
#pragma unroll 1
    for (int c = 0; c < C; c++) {
        float xv0[9], xv1[9];
#pragma unroll
        for (int t = 0; t < 9; t++) {
            xv0[t] = vm0[t] * __ldg(xc0 + off[t]);
            xv1[t] = vm1[t] * __ldg(xc1 + off[t]);
        }
        const float* wp = sw + c*9*28;
#pragma unroll
        for (int t = 0; t < 9; t++) {
            u64 s0 = pk(xv0[t], xv0[t]);
            u64 s1 = pk(xv1[t], xv1[t]);
#pragma unroll
            for (int j = 0; j < 7; j++) {
                float4 w4 = *(const float4*)(wp + t*28 + 4*j);
                u64 wA = pk(w4.x, w4.y);
                u64 wB = pk(w4.z, w4.w);
                acc0[2*j]   = ffma2(s0, wA, acc0[2*j]);
                acc0[2*j+1] = ffma2(s0, wB, acc0[2*j+1]);
                acc1[2*j]   = ffma2(s1, wA, acc1[2*j]);
                acc1[2*j+1] = ffma2(s1, wB, acc1[2*j+1]);
            }
        }
        xc0 += HW; xc1 += HW;
    }
    float* op0 = g_off + (size_t)b*CO_OFF*HW + h0*W + w0;
    float* op1 = op0 + 2*W;
#pragma unroll
    for (int j = 0; j < 13; j++) {
        float2 a = upk(acc0[j]); float2 bq = upk(acc1[j]);
        op0[(2*j)*HW] = a.x;  op0[(2*j+1)*HW] = a.y;
        op1[(2*j)*HW] = bq.x; op1[(2*j+1)*HW] = bq.y;
    }
    op0[26*HW] = upk(acc0[13]).x;
    op1[26*HW] = upk(acc1[13]).x;
}

// ---------------- fused sample + mask + GEMM via mma.sync ----------------
// smem: [0..147456) B blocks; [147456..212992) A double-buffered:
//       buf b at 147456 + b*32768: hi [128px][64ch] bf16 (16KB), lo at +16384
#define SMB   0
#define SMA   147456
#define SMTOT 212992

__global__ __launch_bounds__(512, 1) void k_fused_mma() {
    extern __shared__ char sm[];
    const unsigned sb = smem_u32(sm);
    const int tid  = threadIdx.x;
    const int lane = tid & 31;
    const int warp = tid >> 5;
    const int pxc  = warp & 7;       // px chunk (16 px) this warp's MMAs cover
    const int oh   = warp >> 3;      // o half (32 outputs)

    // stage B once
    {
        const int4* src = (const int4*)g_wB;
        int4* dst = (int4*)(sm + SMB);
        for (int i = tid; i < 147456/16; i += 512) dst[i] = src[i];
    }
    __syncthreads();

    const float2* xp2 = (const float2*)g_xT;

    // constant parts of ldmatrix addresses
    const unsigned a_row = (unsigned)((pxc*16 + (lane & 15))*128 + (lane >> 4)*16);
    const unsigned a_swz = (unsigned)((lane & 7) << 4);
    unsigned b_inner = (unsigned)((lane & 15)*32 + (lane >> 4)*16);
    b_inner ^= ((b_inner >> 7) & 1) << 4;

    for (int t = blockIdx.x; t < NTILE; t += gridDim.x) {
        const int b  = t >> 7;
        const int h  = t & 127;
        const int rb = b * HW;
        const int rowbase = rb + h*W;

        float acc[4][4];
#pragma unroll
        for (int nn = 0; nn < 4; nn++)
#pragma unroll
            for (int j = 0; j < 4; j++) acc[nn][j] = 0.f;

#pragma unroll 1
        for (int k = 0; k < 9; k++) {
            const int buf = k & 1;
            char* aBufH = sm + SMA + buf*32768;
            char* aBufL = aBufH + 16384;

            // ---- params for this warp's 8 px (lanes 0..7) ----
            float4 wt; int4 ix;
            if (lane < 8) {
                int wx = warp*8 + lane;
                int obase = (b*CO_OFF + k)*HW + h*W + wx;
                float o1 = g_off[obase];
                float o2 = g_off[obase +  9*HW];
                float mv = g_off[obase + 18*HW];
                float mask = 1.f / (1.f + expf(-mv));
                int kh = k / 3;
                int kw = k - kh*3;
                float px = o1 + (float)(wx + kw - 1);
                float py = o2 + (float)(h + kh - 1);
                float x0f = floorf(px), y0f = floorf(py);
                int x0 = (int)x0f, y0 = (int)y0f;
                float wx1 = px - x0f, wy1 = py - y0f;
                float wx0 = 1.f - wx1, wy0 = 1.f - wy1;
                float vx0 = (x0 >= 0  && x0     < W) ? 1.f : 0.f;
                float vx1 = (x0 >= -1 && x0 + 1 < W) ? 1.f : 0.f;
                float vy0 = (y0 >= 0  && y0     < H) ? 1.f : 0.f;
                float vy1 = (y0 >= -1 && y0 + 1 < H) ? 1.f : 0.f;
                int cx0 = min(max(x0,   0), W-1);
                int cx1 = min(max(x0+1, 0), W-1);
                int cy0 = min(max(y0,   0), H-1);
                int cy1 = min(max(y0+1, 0), H-1);
                wt.x = wy0*wx0*mask*vy0*vx0;
                wt.y = wy0*wx1*mask*vy0*vx1;
                wt.z = wy1*wx0*mask*vy1*vx0;
                wt.w = wy1*wx1*mask*vy1*vx1;
                ix.x = (rb + cy0*W + cx0) << 5;   // float2 index
                ix.y = (rb + cy0*W + cx1) << 5;
                ix.z = (rb + cy1*W + cx0) << 5;
                ix.w = (rb + cy1*W + cx1) << 5;
            }

            // ---- sample this warp's 8 px, split bf16 hi/lo, STS swizzled ----
#pragma unroll
            for (int p = 0; p < 8; p++) {
                float ax = __shfl_sync(0xffffffffu, wt.x, p);
                float ay = __shfl_sync(0xffffffffu, wt.y, p);
                float az = __shfl_sync(0xffffffffu, wt.z, p);
                float aw = __shfl_sync(0xffffffffu, wt.w, p);
                int q0 = __shfl_sync(0xffffffffu, ix.x, p);
                int q1 = __shfl_sync(0xffffffffu, ix.y, p);
                int q2 = __shfl_sync(0xffffffffu, ix.z, p);
                int q3 = __shfl_sync(0xffffffffu, ix.w, p);
                float2 v00 = xp2[q0 + lane];
                float2 v01 = xp2[q1 + lane];
                float2 v10 = xp2[q2 + lane];
                float2 v11 = xp2[q3 + lane];
                u64 r = fmul2(pk(ax, ax), pk(v00.x, v00.y));
                r = ffma2(pk(ay, ay), pk(v01.x, v01.y), r);
                r = ffma2(pk(az, az), pk(v10.x, v10.y), r);
                r = ffma2(pk(aw, aw), pk(v11.x, v11.y), r);
                float2 v = upk(r);
                unsigned h2 = bf16x2_of(v.x, v.y);
                float hx = __uint_as_float(h2 << 16);
                float hy = __uint_as_float(h2 & 0xffff0000u);
                unsigned l2 = bf16x2_of(v.x - hx, v.y - hy);
                int pxt = warp*8 + p;
                unsigned boff = (unsigned)(pxt*128 + lane*4);
                boff ^= (unsigned)((pxt & 7) << 4);
                *(unsigned*)(aBufH + boff) = h2;
                *(unsigned*)(aBufL + boff) = l2;
            }
            __syncthreads();

            // ---- MMA: 4 kc x 2 n16-blocks x (AhBh + AhBl + AlBh) ----
            const unsigned aBaseH = sb + SMA + buf*32768;
            const unsigned aBaseL = aBaseH + 16384;
            const unsigned bTapH  = sb + SMB + (unsigned)((k*2 + 0)*16)*512;
            const unsigned bTapL  = sb + SMB + (unsigned)((k*2 + 1)*16)*512;
#pragma unroll
            for (int kc = 0; kc < 4; kc++) {
                unsigned ainner = (a_row + kc*32) ^ a_swz;
                unsigned ah0, ah1, ah2, ah3, al0, al1, al2, al3;
                ldsm_x4(ah0, ah1, ah2, ah3, aBaseH + ainner);
                ldsm_x4(al0, al1, al2, al3, aBaseL + ainner);
#pragma unroll
                for (int nb = 0; nb < 2; nb++) {
                    unsigned blkoff = (unsigned)(kc*4 + oh*2 + nb)*512 + b_inner;
                    unsigned bh0, bh1, bh2, bh3, bl0, bl1, bl2, bl3;
                    ldsm_x4t(bh0, bh1, bh2, bh3, bTapH + blkoff);
                    ldsm_x4t(bl0, bl1, bl2, bl3, bTapL + blkoff);
                    mma16816(acc[nb*2+0], ah0, ah1, ah2, ah3, bh0, bh1);
                    mma16816(acc[nb*2+1], ah0, ah1, ah2, ah3, bh2, bh3);
                    mma16816(acc[nb*2+0], ah0, ah1, ah2, ah3, bl0, bl1);
                    mma16816(acc[nb*2+1], ah0, ah1, ah2, ah3, bl2, bl3);
                    mma16816(acc[nb*2+0], al0, al1, al2, al3, bh0, bh1);
                    mma16816(acc[nb*2+1], al0, al1, al2, al3, bh2, bh3);
                }
            }
        }

        // ---- epilogue: registers -> g_y (NHWC) ----
        const int r0 = pxc*16 + (lane >> 2);
        const int ocol = oh*32 + 2*(lane & 3);
#pragma unroll
        for (int nn = 0; nn < 4; nn++) {
            float* d0 = g_y + (size_t)(rowbase + r0)*64 + ocol + nn*8;
            float* d1 = d0 + 8*64;
            *(float2*)d0 = make_float2(acc[nn][0], acc[nn][1]);
            *(float2*)d1 = make_float2(acc[nn][2], acc[nn][3]);
        }
        __syncthreads();   // A buffers reused by next tile's tap 0/1
    }
}

// ---------------- launch ----------------
extern "C" void kernel_launch(void* const* d_in, const int* in_sizes, int n_in,
                              void* d_out, int out_size) {
    const float* x      = (const float*)d_in[0];
    const float* w_off  = (const float*)d_in[1];
    const float* b_off  = (const float*)d_in[2];
    const float* w_conv = (const float*)d_in[3];
    float* out = (float*)d_out;

    const int smem_off = KIDX*28*(int)sizeof(float);   // 64512

    cudaFuncSetAttribute(k_offconv,   cudaFuncAttributeMaxDynamicSharedMemorySize, smem_off);
    cudaFuncSetAttribute(k_fused_mma, cudaFuncAttributeMaxDynamicSharedMemorySize, SMTOT);

    dim3 tgrid(HW/32, C/32, BB);
    dim3 tblk(32, 8);
    k_transpose_in<<<tgrid, tblk>>>(x);
    k_wprep<<<(9*2*64*64 + 255)/256, 256>>>(w_conv);
    k_offconv<<<NPIX/512, 256, smem_off>>>(x, w_off, b_off);
    k_fused_mma<<<152, 512, SMTOT>>>();
    k_transpose_out<<<tgrid, tblk>>>(out);
}

// round 8
// speedup vs baseline: 3.4297x; 1.0428x over previous
#include <cuda_runtime.h>
#include <cuda_bf16.h>
#include <math.h>

#define BB 8
#define C 64
#define H 128
#define W 128
#define HW (H*W)            // 16384
#define NPIX (BB*HW)        // 131072
#define CO_OFF 27
#define KIDX 576
#define NTILE 1024          // 128 px per tile (one image row)

typedef unsigned long long u64;

// ---------------- packed fp32x2 helpers ----------------
__device__ __forceinline__ u64 pk(float x, float y) {
    u64 r; asm("mov.b64 %0, {%1, %2};" : "=l"(r) : "f"(x), "f"(y)); return r;
}
__device__ __forceinline__ float2 upk(u64 a) {
    float2 f; asm("mov.b64 {%0, %1}, %2;" : "=f"(f.x), "=f"(f.y) : "l"(a)); return f;
}
__device__ __forceinline__ u64 ffma2(u64 a, u64 b, u64 c) {
    u64 d; asm("fma.rn.f32x2 %0, %1, %2, %3;" : "=l"(d) : "l"(a), "l"(b), "l"(c)); return d;
}
__device__ __forceinline__ u64 fmul2(u64 a, u64 b) {
    u64 d; asm("mul.rn.f32x2 %0, %1, %2;" : "=l"(d) : "l"(a), "l"(b)); return d;
}
// bf16x2 pack: x -> low half, y -> high half
__device__ __forceinline__ unsigned bf16x2_of(float x, float y) {
    unsigned r; asm("cvt.rn.satfinite.bf16x2.f32 %0, %1, %2;" : "=r"(r) : "f"(y), "f"(x)); return r;
}

// ---------------- mma.sync / ldmatrix (baseline PTX) ----------------
__device__ __forceinline__ void ldsm_x4(unsigned& r0, unsigned& r1, unsigned& r2, unsigned& r3,
                                        unsigned addr) {
    asm volatile("ldmatrix.sync.aligned.m8n8.x4.shared.b16 {%0,%1,%2,%3}, [%4];"
        : "=r"(r0), "=r"(r1), "=r"(r2), "=r"(r3) : "r"(addr));
}
__device__ __forceinline__ void ldsm_x4t(unsigned& r0, unsigned& r1, unsigned& r2, unsigned& r3,
                                         unsigned addr) {
    asm volatile("ldmatrix.sync.aligned.m8n8.x4.trans.shared.b16 {%0,%1,%2,%3}, [%4];"
        : "=r"(r0), "=r"(r1), "=r"(r2), "=r"(r3) : "r"(addr));
}
__device__ __forceinline__ void mma16816(float* c,
                                         unsigned a0, unsigned a1, unsigned a2, unsigned a3,
                                         unsigned b0, unsigned b1) {
    asm volatile(
        "mma.sync.aligned.m16n8k16.row.col.f32.bf16.bf16.f32 "
        "{%0,%1,%2,%3}, {%4,%5,%6,%7}, {%8,%9}, {%0,%1,%2,%3};"
        : "+f"(c[0]), "+f"(c[1]), "+f"(c[2]), "+f"(c[3])
        : "r"(a0), "r"(a1), "r"(a2), "r"(a3), "r"(b0), "r"(b1));
}
__device__ __forceinline__ unsigned smem_u32(const void* p) {
    unsigned a; asm("{ .reg .u64 t; cvta.to.shared.u64 t, %1; cvt.u32.u64 %0, t; }" : "=r"(a) : "l"(p));
    return a;
}
#define MBAR_INIT(mb, n) asm volatile("mbarrier.init.shared.b64 [%0], %1;" :: "r"(mb), "r"(n) : "memory")
#define MBAR_ARRIVE(mb)  asm volatile("mbarrier.arrive.shared.b64 _, [%0];" :: "r"(mb) : "memory")
#define MBAR_WAIT(mb, ph) do { \
    unsigned _mb = (mb), _ph = (ph), _done; \
    asm volatile("{ .reg .pred p; mbarrier.try_wait.parity.acquire.cta.shared::cta.b64 p, [%1], %2; selp.b32 %0, 1, 0, p; }" \
        : "=r"(_done) : "r"(_mb), "r"(_ph) : "memory"); \
    if (!_done) { \
        asm volatile("{ .reg .pred P1; WL_%=: mbarrier.try_wait.parity.acquire.cta.shared::cta.b64 P1, [%0], %1, 0x989680; @P1 bra.uni WD_%=; bra.uni WL_%=; WD_%=: }" \
            :: "r"(_mb), "r"(_ph) : "memory"); \
    } } while (0)

// ---------------- scratch ----------------
__device__ float g_xT[NPIX*C];                            // x NHWC
__device__ float g_off[BB*CO_OFF*HW];                     // offset conv out
__device__ __align__(16) unsigned short g_wB[9*2*64*64];  // W hi/lo, ldmatrix-ready blocks
__device__ float g_y[NPIX*C];                             // result NHWC

// ---------------- NCHW -> NHWC transpose of x ----------------
__global__ void k_transpose_in(const float* __restrict__ x) {
    __shared__ float tile[32][33];
    int b  = blockIdx.z;
    int c0 = blockIdx.y * 32;
    int p0 = blockIdx.x * 32;
    int tx = threadIdx.x, ty = threadIdx.y;
#pragma unroll
    for (int i = 0; i < 4; i++)
        tile[ty + 8*i][tx] = x[(b*C + c0 + ty + 8*i)*HW + p0 + tx];
    __syncthreads();
#pragma unroll
    for (int i = 0; i < 4; i++)
        g_xT[(b*HW + p0 + ty + 8*i)*C + c0 + tx] = tile[tx][ty + 8*i];
}

// ---------------- NHWC -> NCHW transpose of y ----------------
__global__ void k_transpose_out(float* __restrict__ out) {
    __shared__ float tile[32][33];
    int b  = blockIdx.z;
    int c0 = blockIdx.y * 32;
    int p0 = blockIdx.x * 32;
    int tx = threadIdx.x, ty = threadIdx.y;
#pragma unroll
    for (int i = 0; i < 4; i++)
        tile[ty + 8*i][tx] = g_y[(b*HW + p0 + ty + 8*i)*C + c0 + tx];
    __syncthreads();
#pragma unroll
    for (int i = 0; i < 4; i++)
        out[(b*C + c0 + ty + 8*i)*HW + p0 + tx] = tile[tx][ty + 8*i];
}

// ---------------- prep: W -> bf16 hi/lo ldmatrix blocks ----------------
// block(k, hl, kc, n16) = 512B: [16 ch rows][16 o cols] bf16, XOR-swizzled
__global__ void k_wprep(const float* __restrict__ w_conv) {
    int i = blockIdx.x * blockDim.x + threadIdx.x;
    if (i >= 9*2*64*64) return;
    int o  = i & 63;
    int ch = (i >> 6) & 63;
    int hl = (i >> 12) & 1;
    int k  = i >> 13;
    float w = w_conv[o*KIDX + ch*9 + k];
    __nv_bfloat16 hi = __float2bfloat16(w);
    unsigned short val;
    if (hl == 0) {
        val = *(unsigned short*)&hi;
    } else {
        float fhi = __bfloat162float(hi);
        __nv_bfloat16 lo = __float2bfloat16(w - fhi);
        val = *(unsigned short*)&lo;
    }
    unsigned block = (unsigned)(((k*2 + hl)*16) + (ch >> 4)*4 + (o >> 4));
    unsigned inner = (unsigned)((ch & 15)*32 + (o & 15)*2);
    inner ^= ((inner >> 7) & 1) << 4;
    *(unsigned short*)((char*)g_wB + block*512 + inner) = val;
}

// ---------------- offset-predictor 3x3 conv, pad 1, 2 px/thread ----------------
__global__ __launch_bounds__(256) void k_offconv(
    const float* __restrict__ x, const float* __restrict__ w_off,
    const float* __restrict__ b_off)
{
    extern __shared__ float sw[];   // [576][28]
    for (int i = threadIdx.x; i < CO_OFF*KIDX; i += blockDim.x) {
        int co = i / KIDX;
        int r  = i - co*KIDX;
        sw[r*28 + co] = w_off[i];
    }
    __syncthreads();

    int pix0 = blockIdx.x * 512 + threadIdx.x;
    int b  = pix0 >> 14;
    int h0 = (pix0 >> 7) & 127;
    int w0 = pix0 & 127;
    int h1 = h0 + 2;

    int   off[9];
    float vm0[9], vm1[9];
#pragma unroll
    for (int t = 0; t < 9; t++) {
        int dy = t/3 - 1, dx = t%3 - 1;
        off[t] = dy*W + dx;
        int xx = w0 + dx;
        bool vx = (xx >= 0) && (xx < W);
        int y0 = h0 + dy, y1 = h1 + dy;
        vm0[t] = (vx && y0 >= 0 && y0 < H) ? 1.f : 0.f;
        vm1[t] = (vx && y1 >= 0 && y1 < H) ? 1.f : 0.f;
    }

    u64 acc0[14], acc1[14];
#pragma unroll
    for (int j = 0; j < 13; j++) { acc0[j] = pk(b_off[2*j], b_off[2*j+1]); acc1[j] = acc0[j]; }
    acc0[13] = pk(b_off[26], 0.f); acc1[13] = acc0[13];

    const float* xc0 = x + (size_t)b*C*HW + h0*W + w0;
    const float* xc1 = xc0 + 2*W;
#pragma unroll 1
    for (int c = 0; c < C; c++) {
        float xv0[9], xv1[9];
#pragma unroll
        for (int t = 0; t < 9; t++) {
            xv0[t] = vm0[t] * __ldg(xc0 + off[t]);
            xv1[t] = vm1[t] * __ldg(xc1 + off[t]);
        }
        const float* wp = sw + c*9*28;
#pragma unroll
        for (int t = 0; t < 9; t++) {
            u64 s0 = pk(xv0[t], xv0[t]);
            u64 s1 = pk(xv1[t], xv1[t]);
#pragma unroll
            for (int j = 0; j < 7; j++) {
                float4 w4 = *(const float4*)(wp + t*28 + 4*j);
                u64 wA = pk(w4.x, w4.y);
                u64 wB = pk(w4.z, w4.w);
                acc0[2*j]   = ffma2(s0, wA, acc0[2*j]);
                acc0[2*j+1] = ffma2(s0, wB, acc0[2*j+1]);
                acc1[2*j]   = ffma2(s1, wA, acc1[2*j]);
                acc1[2*j+1] = ffma2(s1, wB, acc1[2*j+1]);
            }
        }
        xc0 += HW; xc1 += HW;
    }
    float* op0 = g_off + (size_t)b*CO_OFF*HW + h0*W + w0;
    float* op1 = op0 + 2*W;
#pragma unroll
    for (int j = 0; j < 13; j++) {
        float2 a = upk(acc0[j]); float2 bq = upk(acc1[j]);
        op0[(2*j)*HW] = a.x;  op0[(2*j+1)*HW] = a.y;
        op1[(2*j)*HW] = bq.x; op1[(2*j+1)*HW] = bq.y;
    }
    op0[26*HW] = upk(acc0[13]).x;
    op1[26*HW] = upk(acc1[13]).x;
}

// ---------------- fused: warp-specialized producer/consumer ----------------
// smem: [0..147456) B blocks
//       [147456..212992) A ring, 2 stages x (hi 16KB + lo 16KB)
//       [212992..213024) mbarriers: {full0, empty0, full1, empty1}
#define SMB   0
#define SMA   147456
#define SMQ   212992
#define SMTOT 213056

__global__ __launch_bounds__(512, 1) void k_fused_ws() {
    extern __shared__ char sm[];
    const unsigned sb = smem_u32(sm);
    const int tid  = threadIdx.x;
    const int lane = tid & 31;
    const int warp = tid >> 5;

    // stage B once
    {
        const int4* src = (const int4*)g_wB;
        int4* dst = (int4*)(sm + SMB);
        for (int i = tid; i < 147456/16; i += 512) dst[i] = src[i];
    }
    if (tid == 0) {
        MBAR_INIT(sb + SMQ + 0,  256);   // full0  (producer threads arrive)
        MBAR_INIT(sb + SMQ + 8,  256);   // empty0 (consumer threads arrive)
        MBAR_INIT(sb + SMQ + 16, 256);   // full1
        MBAR_INIT(sb + SMQ + 24, 256);   // empty1
    }
    __syncthreads();

    int stage = 0;

    if (warp < 8) {
        // ================= PRODUCER =================
        int ph = 1;                      // first empty-wait passes immediately
        const float2* xp2 = (const float2*)g_xT;
        for (int t = blockIdx.x; t < NTILE; t += gridDim.x) {
            const int b  = t >> 7;
            const int h  = t & 127;
            const int rb = b * HW;
#pragma unroll 1
            for (int k = 0; k < 9; k++) {
                MBAR_WAIT(sb + SMQ + stage*16 + 8, (unsigned)ph);   // empty[stage]

                // params for this warp's 16 px (lanes 0..15)
                float4 wt; int4 ix;
                if (lane < 16) {
                    int wx = warp*16 + lane;
                    int obase = (b*CO_OFF + k)*HW + h*W + wx;
                    float o1 = g_off[obase];
                    float o2 = g_off[obase +  9*HW];
                    float mv = g_off[obase + 18*HW];
                    float mask = 1.f / (1.f + expf(-mv));
                    int kh = k / 3;
                    int kw = k - kh*3;
                    float px = o1 + (float)(wx + kw - 1);
                    float py = o2 + (float)(h + kh - 1);
                    float x0f = floorf(px), y0f = floorf(py);
                    int x0 = (int)x0f, y0 = (int)y0f;
                    float wx1 = px - x0f, wy1 = py - y0f;
                    float wx0 = 1.f - wx1, wy0 = 1.f - wy1;
                    float vx0 = (x0 >= 0  && x0     < W) ? 1.f : 0.f;
                    float vx1 = (x0 >= -1 && x0 + 1 < W) ? 1.f : 0.f;
                    float vy0 = (y0 >= 0  && y0     < H) ? 1.f : 0.f;
                    float vy1 = (y0 >= -1 && y0 + 1 < H) ? 1.f : 0.f;
                    int cx0 = min(max(x0,   0), W-1);
                    int cx1 = min(max(x0+1, 0), W-1);
                    int cy0 = min(max(y0,   0), H-1);
                    int cy1 = min(max(y0+1, 0), H-1);
                    wt.x = wy0*wx0*mask*vy0*vx0;
                    wt.y = wy0*wx1*mask*vy0*vx1;
                    wt.z = wy1*wx0*mask*vy1*vx0;
                    wt.w = wy1*wx1*mask*vy1*vx1;
                    ix.x = (rb + cy0*W + cx0) << 5;   // float2 index
                    ix.y = (rb + cy0*W + cx1) << 5;
                    ix.z = (rb + cy1*W + cx0) << 5;
                    ix.w = (rb + cy1*W + cx1) << 5;
                }

                char* aBufH = sm + SMA + stage*32768;
                char* aBufL = aBufH + 16384;
#pragma unroll
                for (int p = 0; p < 16; p++) {
                    float ax = __shfl_sync(0xffffffffu, wt.x, p);
                    float ay = __shfl_sync(0xffffffffu, wt.y, p);
                    float az = __shfl_sync(0xffffffffu, wt.z, p);
                    float aw = __shfl_sync(0xffffffffu, wt.w, p);
                    int q0 = __shfl_sync(0xffffffffu, ix.x, p);
                    int q1 = __shfl_sync(0xffffffffu, ix.y, p);
                    int q2 = __shfl_sync(0xffffffffu, ix.z, p);
                    int q3 = __shfl_sync(0xffffffffu, ix.w, p);
                    float2 v00 = xp2[q0 + lane];
                    float2 v01 = xp2[q1 + lane];
                    float2 v10 = xp2[q2 + lane];
                    float2 v11 = xp2[q3 + lane];
                    u64 r = fmul2(pk(ax, ax), pk(v00.x, v00.y));
                    r = ffma2(pk(ay, ay), pk(v01.x, v01.y), r);
                    r = ffma2(pk(az, az), pk(v10.x, v10.y), r);
                    r = ffma2(pk(aw, aw), pk(v11.x, v11.y), r);
                    float2 v = upk(r);
                    unsigned h2 = bf16x2_of(v.x, v.y);
                    float hx = __uint_as_float(h2 << 16);
                    float hy = __uint_as_float(h2 & 0xffff0000u);
                    unsigned l2 = bf16x2_of(v.x - hx, v.y - hy);
                    int pxt = warp*16 + p;
                    unsigned boff = (unsigned)(pxt*128 + lane*4);
                    boff ^= (unsigned)((pxt & 7) << 4);
                    *(unsigned*)(aBufH + boff) = h2;
                    *(unsigned*)(aBufL + boff) = l2;
                }
                MBAR_ARRIVE(sb + SMQ + stage*16);    // full[stage], release
                if (++stage == 2) { stage = 0; ph ^= 1; }
            }
        }
    } else {
        // ================= CONSUMER =================
        int ph = 0;
        const int cw = warp - 8;                     // px chunk: 16*cw .. 16*cw+15
        const unsigned a_row = (unsigned)((cw*16 + (lane & 15))*128 + (lane >> 4)*16);
        const unsigned a_swz = (unsigned)((lane & 7) << 4);
        unsigned b_inner = (unsigned)((lane & 15)*32 + (lane >> 4)*16);
        b_inner ^= ((b_inner >> 7) & 1) << 4;

        for (int t = blockIdx.x; t < NTILE; t += gridDim.x) {
            const int b = t >> 7;
            const int h = t & 127;
            const int rowbase = b*HW + h*W;

            float acc[8][4];
#pragma unroll
            for (int f = 0; f < 8; f++)
#pragma unroll
                for (int j = 0; j < 4; j++) acc[f][j] = 0.f;

#pragma unroll 1
            for (int k = 0; k < 9; k++) {
                MBAR_WAIT(sb + SMQ + stage*16, (unsigned)ph);     // full[stage]
                const unsigned aH = sb + SMA + stage*32768;
                const unsigned aL = aH + 16384;
                const unsigned bH = sb + SMB + (unsigned)(k*2)*8192;
                const unsigned bL = bH + 8192;
#pragma unroll
                for (int kc = 0; kc < 4; kc++) {
                    unsigned ainner = (a_row + kc*32) ^ a_swz;
                    unsigned ah0, ah1, ah2, ah3, al0, al1, al2, al3;
                    ldsm_x4(ah0, ah1, ah2, ah3, aH + ainner);
                    ldsm_x4(al0, al1, al2, al3, aL + ainner);
#pragma unroll
                    for (int nb = 0; nb < 4; nb++) {
                        unsigned blk = (unsigned)(kc*4 + nb)*512 + b_inner;
                        unsigned bh0, bh1, bh2, bh3, bl0, bl1, bl2, bl3;
                        ldsm_x4t(bh0, bh1, bh2, bh3, bH + blk);
                        ldsm_x4t(bl0, bl1, bl2, bl3, bL + blk);
                        mma16816(acc[nb*2+0], ah0, ah1, ah2, ah3, bh0, bh1);
                        mma16816(acc[nb*2+1], ah0, ah1, ah2, ah3, bh2, bh3);
                        mma16816(acc[nb*2+0], ah0, ah1, ah2, ah3, bl0, bl1);
                        mma16816(acc[nb*2+1], ah0, ah1, ah2, ah3, bl2, bl3);
                        mma16816(acc[nb*2+0], al0, al1, al2, al3, bh0, bh1);
                        mma16816(acc[nb*2+1], al0, al1, al2, al3, bh2, bh3);
                    }
                }
                MBAR_ARRIVE(sb + SMQ + stage*16 + 8);   // empty[stage]
                if (++stage == 2) { stage = 0; ph ^= 1; }
            }

            // epilogue: registers -> g_y (NHWC)
            const int r0 = cw*16 + (lane >> 2);
            const int oc = 2*(lane & 3);
#pragma unroll
            for (int f = 0; f < 8; f++) {
                float* d0 = g_y + (size_t)(rowbase + r0)*64 + f*8 + oc;
                float* d1 = d0 + 8*64;
                *(float2*)d0 = make_float2(acc[f][0], acc[f][1]);
                *(float2*)d1 = make_float2(acc[f][2], acc[f][3]);
            }
        }
    }
}

// ---------------- launch ----------------
extern "C" void kernel_launch(void* const* d_in, const int* in_sizes, int n_in,
                              void* d_out, int out_size) {
    const float* x      = (const float*)d_in[0];
    const float* w_off  = (const float*)d_in[1];
    const float* b_off  = (const float*)d_in[2];
    const float* w_conv = (const float*)d_in[3];
    float* out = (float*)d_out;

    const int smem_off = KIDX*28*(int)sizeof(float);   // 64512

    cudaFuncSetAttribute(k_offconv,  cudaFuncAttributeMaxDynamicSharedMemorySize, smem_off);
    cudaFuncSetAttribute(k_fused_ws, cudaFuncAttributeMaxDynamicSharedMemorySize, SMTOT);

    dim3 tgrid(HW/32, C/32, BB);
    dim3 tblk(32, 8);
    k_transpose_in<<<tgrid, tblk>>>(x);
    k_wprep<<<(9*2*64*64 + 255)/256, 256>>>(w_conv);
    k_offconv<<<NPIX/512, 256, smem_off>>>(x, w_off, b_off);
    k_fused_ws<<<152, 512, SMTOT>>>();
    k_transpose_out<<<tgrid, tblk>>>(out);
}

// round 9
// speedup vs baseline: 3.5127x; 1.0242x over previous
#include <cuda_runtime.h>
#include <cuda_bf16.h>
#include <math.h>

#define BB 8
#define C 64
#define H 128
#define W 128
#define HW (H*W)            // 16384
#define NPIX (BB*HW)        // 131072
#define CO_OFF 27
#define KIDX 576
#define NTILE 1024          // 128 px per tile (one image row)

typedef unsigned long long u64;

// ---------------- packed fp32x2 helpers ----------------
__device__ __forceinline__ u64 pk(float x, float y) {
    u64 r; asm("mov.b64 %0, {%1, %2};" : "=l"(r) : "f"(x), "f"(y)); return r;
}
__device__ __forceinline__ float2 upk(u64 a) {
    float2 f; asm("mov.b64 {%0, %1}, %2;" : "=f"(f.x), "=f"(f.y) : "l"(a)); return f;
}
__device__ __forceinline__ u64 ffma2(u64 a, u64 b, u64 c) {
    u64 d; asm("fma.rn.f32x2 %0, %1, %2, %3;" : "=l"(d) : "l"(a), "l"(b), "l"(c)); return d;
}
__device__ __forceinline__ u64 fmul2(u64 a, u64 b) {
    u64 d; asm("mul.rn.f32x2 %0, %1, %2;" : "=l"(d) : "l"(a), "l"(b)); return d;
}
// bf16x2 pack: x -> low half, y -> high half
__device__ __forceinline__ unsigned bf16x2_of(float x, float y) {
    unsigned r; asm("cvt.rn.satfinite.bf16x2.f32 %0, %1, %2;" : "=r"(r) : "f"(y), "f"(x)); return r;
}

// ---------------- mma.sync / ldmatrix (baseline PTX) ----------------
__device__ __forceinline__ void ldsm_x4(unsigned& r0, unsigned& r1, unsigned& r2, unsigned& r3,
                                        unsigned addr) {
    asm volatile("ldmatrix.sync.aligned.m8n8.x4.shared.b16 {%0,%1,%2,%3}, [%4];"
        : "=r"(r0), "=r"(r1), "=r"(r2), "=r"(r3) : "r"(addr));
}
__device__ __forceinline__ void ldsm_x4t(unsigned& r0, unsigned& r1, unsigned& r2, unsigned& r3,
                                         unsigned addr) {
    asm volatile("ldmatrix.sync.aligned.m8n8.x4.trans.shared.b16 {%0,%1,%2,%3}, [%4];"
        : "=r"(r0), "=r"(r1), "=r"(r2), "=r"(r3) : "r"(addr));
}
__device__ __forceinline__ void mma16816(float* c,
                                         unsigned a0, unsigned a1, unsigned a2, unsigned a3,
                                         unsigned b0, unsigned b1) {
    asm volatile(
        "mma.sync.aligned.m16n8k16.row.col.f32.bf16.bf16.f32 "
        "{%0,%1,%2,%3}, {%4,%5,%6,%7}, {%8,%9}, {%0,%1,%2,%3};"
        : "+f"(c[0]), "+f"(c[1]), "+f"(c[2]), "+f"(c[3])
        : "r"(a0), "r"(a1), "r"(a2), "r"(a3), "r"(b0), "r"(b1));
}
__device__ __forceinline__ unsigned smem_u32(const void* p) {
    unsigned a; asm("{ .reg .u64 t; cvta.to.shared.u64 t, %1; cvt.u32.u64 %0, t; }" : "=r"(a) : "l"(p));
    return a;
}
#define MBAR_INIT(mb, n) asm volatile("mbarrier.init.shared.b64 [%0], %1;" :: "r"(mb), "r"(n) : "memory")
#define MBAR_ARRIVE(mb)  asm volatile("mbarrier.arrive.shared.b64 _, [%0];" :: "r"(mb) : "memory")
#define MBAR_WAIT(mb, ph) do { \
    unsigned _mb = (mb), _ph = (ph), _done; \
    asm volatile("{ .reg .pred p; mbarrier.try_wait.parity.acquire.cta.shared::cta.b64 p, [%1], %2; selp.b32 %0, 1, 0, p; }" \
        : "=r"(_done) : "r"(_mb), "r"(_ph) : "memory"); \
    if (!_done) { \
        asm volatile("{ .reg .pred P1; WL_%=: mbarrier.try_wait.parity.acquire.cta.shared::cta.b64 P1, [%0], %1, 0x989680; @P1 bra.uni WD_%=; bra.uni WL_%=; WD_%=: }" \
            :: "r"(_mb), "r"(_ph) : "memory"); \
    } } while (0)

// ---------------- scratch ----------------
__device__ float g_xT[NPIX*C];                            // x NHWC
__device__ float g_off[BB*CO_OFF*HW];                     // offset conv out
__device__ __align__(16) unsigned short g_wB[9*2*64*64];  // W hi/lo, ldmatrix-ready blocks
__device__ float g_y[NPIX*C];                             // result NHWC

// ---------------- NCHW -> NHWC transpose of x ----------------
__global__ void k_transpose_in(const float* __restrict__ x) {
    __shared__ float tile[32][33];
    int b  = blockIdx.z;
    int c0 = blockIdx.y * 32;
    int p0 = blockIdx.x * 32;
    int tx = threadIdx.x, ty = threadIdx.y;
#pragma unroll
    for (int i = 0; i < 4; i++)
        tile[ty + 8*i][tx] = x[(b*C + c0 + ty + 8*i)*HW + p0 + tx];
    __syncthreads();
#pragma unroll
    for (int i = 0; i < 4; i++)
        g_xT[(b*HW + p0 + ty + 8*i)*C + c0 + tx] = tile[tx][ty + 8*i];
}

// ---------------- NHWC -> NCHW transpose of y ----------------
__global__ void k_transpose_out(float* __restrict__ out) {
    __shared__ float tile[32][33];
    int b  = blockIdx.z;
    int c0 = blockIdx.y * 32;
    int p0 = blockIdx.x * 32;
    int tx = threadIdx.x, ty = threadIdx.y;
#pragma unroll
    for (int i = 0; i < 4; i++)
        tile[ty + 8*i][tx] = g_y[(b*HW + p0 + ty + 8*i)*C + c0 + tx];
    __syncthreads();
#pragma unroll
    for (int i = 0; i < 4; i++)
        out[(b*C + c0 + ty + 8*i)*HW + p0 + tx] = tile[tx][ty + 8*i];
}

// ---------------- prep: W -> bf16 hi/lo ldmatrix blocks ----------------
// block(k, hl, kc, n16) = 512B: [16 ch rows][16 o cols] bf16, XOR-swizzled
__global__ void k_wprep(const float* __restrict__ w_conv) {
    int i = blockIdx.x * blockDim.x + threadIdx.x;
    if (i >= 9*2*64*64) return;
    int o  = i & 63;
    int ch = (i >> 6) & 63;
    int hl = (i >> 12) & 1;
    int k  = i >> 13;
    float w = w_conv[o*KIDX + ch*9 + k];
    __nv_bfloat16 hi = __float2bfloat16(w);
    unsigned short val;
    if (hl == 0) {
        val = *(unsigned short*)&hi;
    } else {
        float fhi = __bfloat162float(hi);
        __nv_bfloat16 lo = __float2bfloat16(w - fhi);
        val = *(unsigned short*)&lo;
    }
    unsigned block = (unsigned)(((k*2 + hl)*16) + (ch >> 4)*4 + (o >> 4));
    unsigned inner = (unsigned)((ch & 15)*32 + (o & 15)*2);
    inner ^= ((inner >> 7) & 1) << 4;
    *(unsigned short*)((char*)g_wB + block*512 + inner) = val;
}

// ---------------- offset-predictor 3x3 conv, pad 1, 2 px/thread ----------------
__global__ __launch_bounds__(256) void k_offconv(
    const float* __restrict__ x, const float* __restrict__ w_off,
    const float* __restrict__ b_off)
{
    extern __shared__ float sw[];   // [576][28]
    for (int i = threadIdx.x; i < CO_OFF*KIDX; i += blockDim.x) {
        int co = i / KIDX;
        int r  = i - co*KIDX;
        sw[r*28 + co] = w_off[i];
    }
    __syncthreads();

    int pix0 = blockIdx.x * 512 + threadIdx.x;
    int b  = pix0 >> 14;
    int h0 = (pix0 >> 7) & 127;
    int w0 = pix0 & 127;
    int h1 = h0 + 2;

    int   off[9];
    float vm0[9], vm1[9];
#pragma unroll
    for (int t = 0; t < 9; t++) {
        int dy = t/3 - 1, dx = t%3 - 1;
        off[t] = dy*W + dx;
        int xx = w0 + dx;
        bool vx = (xx >= 0) && (xx < W);
        int y0 = h0 + dy, y1 = h1 + dy;
        vm0[t] = (vx && y0 >= 0 && y0 < H) ? 1.f : 0.f;
        vm1[t] = (vx && y1 >= 0 && y1 < H) ? 1.f : 0.f;
    }

    u64 acc0[14], acc1[14];
#pragma unroll
    for (int j = 0; j < 13; j++) { acc0[j] = pk(b_off[2*j], b_off[2*j+1]); acc1[j] = acc0[j]; }
    acc0[13] = pk(b_off[26], 0.f); acc1[13] = acc0[13];

    const float* xc0 = x + (size_t)b*C*HW + h0*W + w0;
    const float* xc1 = xc0 + 2*W;
#pragma unroll 1
    for (int c = 0; c < C; c++) {
        float xv0[9], xv1[9];
#pragma unroll
        for (int t = 0; t < 9; t++) {
            xv0[t] = vm0[t] * __ldg(xc0 + off[t]);
            xv1[t] = vm1[t] * __ldg(xc1 + off[t]);
        }
        const float* wp = sw + c*9*28;
#pragma unroll
        for (int t = 0; t < 9; t++) {
            u64 s0 = pk(xv0[t], xv0[t]);
            u64 s1 = pk(xv1[t], xv1[t]);
#pragma unroll
            for (int j = 0; j < 7; j++) {
                float4 w4 = *(const float4*)(wp + t*28 + 4*j);
                u64 wA = pk(w4.x, w4.y);
                u64 wB = pk(w4.z, w4.w);
                acc0[2*j]   = ffma2(s0, wA, acc0[2*j]);
                acc0[2*j+1] = ffma2(s0, wB, acc0[2*j+1]);
                acc1[2*j]   = ffma2(s1, wA, acc1[2*j]);
                acc1[2*j+1] = ffma2(s1, wB, acc1[2*j+1]);
            }
        }
        xc0 += HW; xc1 += HW;
    }
    float* op0 = g_off + (size_t)b*CO_OFF*HW + h0*W + w0;
    float* op1 = op0 + 2*W;
#pragma unroll
    for (int j = 0; j < 13; j++) {
        float2 a = upk(acc0[j]); float2 bq = upk(acc1[j]);
        op0[(2*j)*HW] = a.x;  op0[(2*j+1)*HW] = a.y;
        op1[(2*j)*HW] = bq.x; op1[(2*j+1)*HW] = bq.y;
    }
    op0[26*HW] = upk(acc0[13]).x;
    op1[26*HW] = upk(acc1[13]).x;
}

// ---------------- fused: warp-specialized producer/consumer ----------------
// smem: [0..147456) B blocks
//       [147456..212992) A ring, 2 stages x (hi 16KB + lo 16KB)
//       [212992..213024) mbarriers: {full0, empty0, full1, empty1}
#define SMB   0
#define SMA   147456
#define SMQ   212992
#define SMTOT 213056

__global__ __launch_bounds__(512, 1) void k_fused_ws() {
    extern __shared__ char sm[];
    const unsigned sb = smem_u32(sm);
    const int tid  = threadIdx.x;
    const int lane = tid & 31;
    const int warp = tid >> 5;

    // stage B once
    {
        const int4* src = (const int4*)g_wB;
        int4* dst = (int4*)(sm + SMB);
        for (int i = tid; i < 147456/16; i += 512) dst[i] = src[i];
    }
    if (tid == 0) {
        MBAR_INIT(sb + SMQ + 0,  256);   // full0  (producer threads arrive)
        MBAR_INIT(sb + SMQ + 8,  256);   // empty0 (consumer threads arrive)
        MBAR_INIT(sb + SMQ + 16, 256);   // full1
        MBAR_INIT(sb + SMQ + 24, 256);   // empty1
    }
    __syncthreads();

    int stage = 0;

    if (warp < 8) {
        // ================= PRODUCER =================
        int ph = 1;                      // first empty-wait passes immediately
        const float2* xp2 = (const float2*)g_xT;
        for (int t = blockIdx.x; t < NTILE; t += gridDim.x) {
            const int b  = t >> 7;
            const int h  = t & 127;
            const int rb = b * HW;
            const int wx = warp*16 + lane;              // lane<16 only
            const int obase0 = b*CO_OFF*HW + h*W + wx;

            // preload tap-0 offset params
            float no1 = 0.f, no2 = 0.f, nmv = 0.f;
            if (lane < 16) {
                no1 = __ldg(g_off + obase0);
                no2 = __ldg(g_off + obase0 +  9*HW);
                nmv = __ldg(g_off + obase0 + 18*HW);
            }

#pragma unroll 1
            for (int k = 0; k < 9; k++) {
                float o1 = no1, o2 = no2, mv = nmv;
                if (k < 8 && lane < 16) {               // prefetch next tap's params
                    int ob = obase0 + (k+1)*HW;
                    no1 = __ldg(g_off + ob);
                    no2 = __ldg(g_off + ob +  9*HW);
                    nmv = __ldg(g_off + ob + 18*HW);
                }

                // params for this warp's 16 px (lanes 0..15)
                float4 wt; int4 ix;
                {
                    float mask = 1.f / (1.f + expf(-mv));
                    int kh = k / 3;
                    int kw = k - kh*3;
                    float px = o1 + (float)(wx + kw - 1);
                    float py = o2 + (float)(h + kh - 1);
                    float x0f = floorf(px), y0f = floorf(py);
                    int x0 = (int)x0f, y0 = (int)y0f;
                    float wx1 = px - x0f, wy1 = py - y0f;
                    float wx0 = 1.f - wx1, wy0 = 1.f - wy1;
                    float vx0 = (x0 >= 0  && x0     < W) ? 1.f : 0.f;
                    float vx1 = (x0 >= -1 && x0 + 1 < W) ? 1.f : 0.f;
                    float vy0 = (y0 >= 0  && y0     < H) ? 1.f : 0.f;
                    float vy1 = (y0 >= -1 && y0 + 1 < H) ? 1.f : 0.f;
                    int cx0 = min(max(x0,   0), W-1);
                    int cx1 = min(max(x0+1, 0), W-1);
                    int cy0 = min(max(y0,   0), H-1);
                    int cy1 = min(max(y0+1, 0), H-1);
                    wt.x = wy0*wx0*mask*vy0*vx0;
                    wt.y = wy0*wx1*mask*vy0*vx1;
                    wt.z = wy1*wx0*mask*vy1*vx0;
                    wt.w = wy1*wx1*mask*vy1*vx1;
                    ix.x = (rb + cy0*W + cx0) << 5;   // float2 index
                    ix.y = (rb + cy0*W + cx1) << 5;
                    ix.z = (rb + cy1*W + cx0) << 5;
                    ix.w = (rb + cy1*W + cx1) << 5;
                }

                // pipelined gathers: 4-px batches, 2-batch lookahead
                float2 c[3][16];
#define P_ISSUE(bi, p4) { \
    _Pragma("unroll") \
    for (int j = 0; j < 4; j++) { \
        int pp = (p4)*4 + j; \
        int q0 = __shfl_sync(0xffffffffu, ix.x, pp); \
        int q1 = __shfl_sync(0xffffffffu, ix.y, pp); \
        int q2 = __shfl_sync(0xffffffffu, ix.z, pp); \
        int q3 = __shfl_sync(0xffffffffu, ix.w, pp); \
        c[bi][j*4+0] = xp2[q0 + lane]; \
        c[bi][j*4+1] = xp2[q1 + lane]; \
        c[bi][j*4+2] = xp2[q2 + lane]; \
        c[bi][j*4+3] = xp2[q3 + lane]; \
    } }
#define P_COMBINE(bi, p4) { \
    _Pragma("unroll") \
    for (int j = 0; j < 4; j++) { \
        int pp = (p4)*4 + j; \
        float ax = __shfl_sync(0xffffffffu, wt.x, pp); \
        float ay = __shfl_sync(0xffffffffu, wt.y, pp); \
        float az = __shfl_sync(0xffffffffu, wt.z, pp); \
        float aw = __shfl_sync(0xffffffffu, wt.w, pp); \
        u64 r = fmul2(pk(ax, ax), pk(c[bi][j*4+0].x, c[bi][j*4+0].y)); \
        r = ffma2(pk(ay, ay), pk(c[bi][j*4+1].x, c[bi][j*4+1].y), r); \
        r = ffma2(pk(az, az), pk(c[bi][j*4+2].x, c[bi][j*4+2].y), r); \
        r = ffma2(pk(aw, aw), pk(c[bi][j*4+3].x, c[bi][j*4+3].y), r); \
        float2 v = upk(r); \
        unsigned h2 = bf16x2_of(v.x, v.y); \
        float hx = __uint_as_float(h2 << 16); \
        float hy = __uint_as_float(h2 & 0xffff0000u); \
        unsigned l2 = bf16x2_of(v.x - hx, v.y - hy); \
        int pxt = warp*16 + pp; \
        unsigned boff = (unsigned)(pxt*128 + lane*4); \
        boff ^= (unsigned)((pxt & 7) << 4); \
        *(unsigned*)(aBufH + boff) = h2; \
        *(unsigned*)(aBufL + boff) = l2; \
    } }

                // issue first two batches BEFORE waiting (LDGs don't touch smem)
                P_ISSUE(0, 0);
                P_ISSUE(1, 1);
                MBAR_WAIT(sb + SMQ + stage*16 + 8, (unsigned)ph);   // empty[stage]
                char* aBufH = sm + SMA + stage*32768;
                char* aBufL = aBufH + 16384;
                P_ISSUE(2, 2);
                P_COMBINE(0, 0);
                P_ISSUE(0, 3);
                P_COMBINE(1, 1);
                P_COMBINE(2, 2);
                P_COMBINE(0, 3);
#undef P_ISSUE
#undef P_COMBINE
                MBAR_ARRIVE(sb + SMQ + stage*16);    // full[stage], release
                if (++stage == 2) { stage = 0; ph ^= 1; }
            }
        }
    } else {
        // ================= CONSUMER =================
        int ph = 0;
        const int cw  = warp - 8;
        const int pxc = cw & 3;          // 32-px chunk
        const int oh  = cw >> 2;         // 32-o half
        const unsigned a_row0 = (unsigned)((pxc*32 + (lane & 15))*128 + (lane >> 4)*16);
        const unsigned a_row1 = a_row0 + 16*128;
        const unsigned a_swz  = (unsigned)((lane & 7) << 4);
        unsigned b_inner = (unsigned)((lane & 15)*32 + (lane >> 4)*16);
        b_inner ^= ((b_inner >> 7) & 1) << 4;

        for (int t = blockIdx.x; t < NTILE; t += gridDim.x) {
            const int b = t >> 7;
            const int h = t & 127;
            const int rowbase = b*HW + h*W;

            float acc[2][4][4];
#pragma unroll
            for (int m = 0; m < 2; m++)
#pragma unroll
                for (int f = 0; f < 4; f++)
#pragma unroll
                    for (int j = 0; j < 4; j++) acc[m][f][j] = 0.f;

#pragma unroll 1
            for (int k = 0; k < 9; k++) {
                MBAR_WAIT(sb + SMQ + stage*16, (unsigned)ph);     // full[stage]
                const unsigned aH = sb + SMA + stage*32768;
                const unsigned aL = aH + 16384;
                const unsigned bH = sb + SMB + (unsigned)(k*2)*8192;
                const unsigned bL = bH + 8192;
#pragma unroll
                for (int kc = 0; kc < 4; kc++) {
                    unsigned ai0 = (a_row0 + kc*32) ^ a_swz;
                    unsigned ai1 = (a_row1 + kc*32) ^ a_swz;
                    unsigned a0h0,a0h1,a0h2,a0h3, a0l0,a0l1,a0l2,a0l3;
                    unsigned a1h0,a1h1,a1h2,a1h3, a1l0,a1l1,a1l2,a1l3;
                    ldsm_x4(a0h0,a0h1,a0h2,a0h3, aH + ai0);
                    ldsm_x4(a0l0,a0l1,a0l2,a0l3, aL + ai0);
                    ldsm_x4(a1h0,a1h1,a1h2,a1h3, aH + ai1);
                    ldsm_x4(a1l0,a1l1,a1l2,a1l3, aL + ai1);
#pragma unroll
                    for (int nb = 0; nb < 2; nb++) {
                        unsigned blk = (unsigned)(kc*4 + oh*2 + nb)*512 + b_inner;
                        unsigned bh0,bh1,bh2,bh3, bl0,bl1,bl2,bl3;
                        ldsm_x4t(bh0,bh1,bh2,bh3, bH + blk);
                        ldsm_x4t(bl0,bl1,bl2,bl3, bL + blk);
                        // m-block 0
                        mma16816(acc[0][nb*2+0], a0h0,a0h1,a0h2,a0h3, bh0,bh1);
                        mma16816(acc[0][nb*2+1], a0h0,a0h1,a0h2,a0h3, bh2,bh3);
                        mma16816(acc[0][nb*2+0], a0h0,a0h1,a0h2,a0h3, bl0,bl1);
                        mma16816(acc[0][nb*2+1], a0h0,a0h1,a0h2,a0h3, bl2,bl3);
                        mma16816(acc[0][nb*2+0], a0l0,a0l1,a0l2,a0l3, bh0,bh1);
                        mma16816(acc[0][nb*2+1], a0l0,a0l1,a0l2,a0l3, bh2,bh3);
                        // m-block 1
                        mma16816(acc[1][nb*2+0], a1h0,a1h1,a1h2,a1h3, bh0,bh1);
                        mma16816(acc[1][nb*2+1], a1h0,a1h1,a1h2,a1h3, bh2,bh3);
                        mma16816(acc[1][nb*2+0], a1h0,a1h1,a1h2,a1h3, bl0,bl1);
                        mma16816(acc[1][nb*2+1], a1h0,a1h1,a1h2,a1h3, bl2,bl3);
                        mma16816(acc[1][nb*2+0], a1l0,a1l1,a1l2,a1l3, bh0,bh1);
                        mma16816(acc[1][nb*2+1], a1l0,a1l1,a1l2,a1l3, bh2,bh3);
                    }
                }
                MBAR_ARRIVE(sb + SMQ + stage*16 + 8);   // empty[stage]
                if (++stage == 2) { stage = 0; ph ^= 1; }
            }

            // epilogue: registers -> g_y (NHWC)
            const int oc0 = oh*32 + 2*(lane & 3);
#pragma unroll
            for (int m = 0; m < 2; m++) {
                const int r0 = pxc*32 + m*16 + (lane >> 2);
#pragma unroll
                for (int f = 0; f < 4; f++) {
                    int oc = oc0 + (f >> 1)*16 + (f & 1)*8;
                    float* d0 = g_y + (size_t)(rowbase + r0)*64 + oc;
                    float* d1 = d0 + 8*64;
                    *(float2*)d0 = make_float2(acc[m][f][0], acc[m][f][1]);
                    *(float2*)d1 = make_float2(acc[m][f][2], acc[m][f][3]);
                }
            }
        }
    }
}

// ---------------- launch ----------------
extern "C" void kernel_launch(void* const* d_in, const int* in_sizes, int n_in,
                              void* d_out, int out_size) {
    const float* x      = (const float*)d_in[0];
    const float* w_off  = (const float*)d_in[1];
    const float* b_off  = (const float*)d_in[2];
    const float* w_conv = (const float*)d_in[3];
    float* out = (float*)d_out;

    const int smem_off = KIDX*28*(int)sizeof(float);   // 64512

    cudaFuncSetAttribute(k_offconv,  cudaFuncAttributeMaxDynamicSharedMemorySize, smem_off);
    cudaFuncSetAttribute(k_fused_ws, cudaFuncAttributeMaxDynamicSharedMemorySize, SMTOT);

    dim3 tgrid(HW/32, C/32, BB);
    dim3 tblk(32, 8);
    k_transpose_in<<<tgrid, tblk>>>(x);
    k_wprep<<<(9*2*64*64 + 255)/256, 256>>>(w_conv);
    k_offconv<<<NPIX/512, 256, smem_off>>>(x, w_off, b_off);
    k_fused_ws<<<152, 512, SMTOT>>>();
    k_transpose_out<<<tgrid, tblk>>>(out);
}

// round 10
// speedup vs baseline: 3.5364x; 1.0067x over previous
#include <cuda_runtime.h>
#include <cuda_bf16.h>
#include <math.h>

#define BB 8
#define C 64
#define H 128
#define W 128
#define HW (H*W)            // 16384
#define NPIX (BB*HW)        // 131072
#define CO_OFF 27
#define KIDX 576
#define NTILE 1024          // 128 px per tile (one image row)

typedef unsigned long long u64;

// ---------------- packed fp32x2 helpers ----------------
__device__ __forceinline__ u64 pk(float x, float y) {
    u64 r; asm("mov.b64 %0, {%1, %2};" : "=l"(r) : "f"(x), "f"(y)); return r;
}
__device__ __forceinline__ float2 upk(u64 a) {
    float2 f; asm("mov.b64 {%0, %1}, %2;" : "=f"(f.x), "=f"(f.y) : "l"(a)); return f;
}
__device__ __forceinline__ u64 ffma2(u64 a, u64 b, u64 c) {
    u64 d; asm("fma.rn.f32x2 %0, %1, %2, %3;" : "=l"(d) : "l"(a), "l"(b), "l"(c)); return d;
}
__device__ __forceinline__ u64 fmul2(u64 a, u64 b) {
    u64 d; asm("mul.rn.f32x2 %0, %1, %2;" : "=l"(d) : "l"(a), "l"(b)); return d;
}
// bf16x2 pack: x -> low half, y -> high half
__device__ __forceinline__ unsigned bf16x2_of(float x, float y) {
    unsigned r; asm("cvt.rn.satfinite.bf16x2.f32 %0, %1, %2;" : "=r"(r) : "f"(y), "f"(x)); return r;
}

// ---------------- mma.sync / ldmatrix (baseline PTX) ----------------
__device__ __forceinline__ void ldsm_x4(unsigned& r0, unsigned& r1, unsigned& r2, unsigned& r3,
                                        unsigned addr) {
    asm volatile("ldmatrix.sync.aligned.m8n8.x4.shared.b16 {%0,%1,%2,%3}, [%4];"
        : "=r"(r0), "=r"(r1), "=r"(r2), "=r"(r3) : "r"(addr));
}
__device__ __forceinline__ void ldsm_x4t(unsigned& r0, unsigned& r1, unsigned& r2, unsigned& r3,
                                         unsigned addr) {
    asm volatile("ldmatrix.sync.aligned.m8n8.x4.trans.shared.b16 {%0,%1,%2,%3}, [%4];"
        : "=r"(r0), "=r"(r1), "=r"(r2), "=r"(r3) : "r"(addr));
}
__device__ __forceinline__ void mma16816(float* c,
                                         unsigned a0, unsigned a1, unsigned a2, unsigned a3,
                                         unsigned b0, unsigned b1) {
    asm volatile(
        "mma.sync.aligned.m16n8k16.row.col.f32.bf16.bf16.f32 "
        "{%0,%1,%2,%3}, {%4,%5,%6,%7}, {%8,%9}, {%0,%1,%2,%3};"
        : "+f"(c[0]), "+f"(c[1]), "+f"(c[2]), "+f"(c[3])
        : "r"(a0), "r"(a1), "r"(a2), "r"(a3), "r"(b0), "r"(b1));
}
__device__ __forceinline__ unsigned smem_u32(const void* p) {
    unsigned a; asm("{ .reg .u64 t; cvta.to.shared.u64 t, %1; cvt.u32.u64 %0, t; }" : "=r"(a) : "l"(p));
    return a;
}
#define MBAR_INIT(mb, n) asm volatile("mbarrier.init.shared.b64 [%0], %1;" :: "r"(mb), "r"(n) : "memory")
#define MBAR_ARRIVE(mb)  asm volatile("mbarrier.arrive.shared.b64 _, [%0];" :: "r"(mb) : "memory")
#define MBAR_WAIT(mb, ph) do { \
    unsigned _mb = (mb), _ph = (ph), _done; \
    asm volatile("{ .reg .pred p; mbarrier.try_wait.parity.acquire.cta.shared::cta.b64 p, [%1], %2; selp.b32 %0, 1, 0, p; }" \
        : "=r"(_done) : "r"(_mb), "r"(_ph) : "memory"); \
    if (!_done) { \
        asm volatile("{ .reg .pred P1; WL_%=: mbarrier.try_wait.parity.acquire.cta.shared::cta.b64 P1, [%0], %1, 0x989680; @P1 bra.uni WD_%=; bra.uni WL_%=; WD_%=: }" \
            :: "r"(_mb), "r"(_ph) : "memory"); \
    } } while (0)
#define CP_ASYNC16(dst, src) \
    asm volatile("cp.async.ca.shared.global [%0], [%1], 16;" :: "r"(dst), "l"(src) : "memory")
#define CP_COMMIT()  asm volatile("cp.async.commit_group;" ::: "memory")
#define CP_WAIT0()   asm volatile("cp.async.wait_group 0;" ::: "memory")

// ---------------- scratch ----------------
__device__ float g_xT[NPIX*C];                            // x NHWC
__device__ float g_off[BB*CO_OFF*HW];                     // offset conv out
__device__ __align__(16) unsigned short g_wB[9*2*64*64];  // W hi/lo, ldmatrix-ready blocks
__device__ float g_y[NPIX*C];                             // result NHWC

// ---------------- NCHW -> NHWC transpose of x ----------------
__global__ void k_transpose_in(const float* __restrict__ x) {
    __shared__ float tile[32][33];
    int b  = blockIdx.z;
    int c0 = blockIdx.y * 32;
    int p0 = blockIdx.x * 32;
    int tx = threadIdx.x, ty = threadIdx.y;
#pragma unroll
    for (int i = 0; i < 4; i++)
        tile[ty + 8*i][tx] = x[(b*C + c0 + ty + 8*i)*HW + p0 + tx];
    __syncthreads();
#pragma unroll
    for (int i = 0; i < 4; i++)
        g_xT[(b*HW + p0 + ty + 8*i)*C + c0 + tx] = tile[tx][ty + 8*i];
}

// ---------------- NHWC -> NCHW transpose of y ----------------
__global__ void k_transpose_out(float* __restrict__ out) {
    __shared__ float tile[32][33];
    int b  = blockIdx.z;
    int c0 = blockIdx.y * 32;
    int p0 = blockIdx.x * 32;
    int tx = threadIdx.x, ty = threadIdx.y;
#pragma unroll
    for (int i = 0; i < 4; i++)
        tile[ty + 8*i][tx] = g_y[(b*HW + p0 + ty + 8*i)*C + c0 + tx];
    __syncthreads();
#pragma unroll
    for (int i = 0; i < 4; i++)
        out[(b*C + c0 + ty + 8*i)*HW + p0 + tx] = tile[tx][ty + 8*i];
}

// ---------------- prep: W -> bf16 hi/lo ldmatrix blocks ----------------
// block(k, hl, kc, n16) = 512B: [16 ch rows][16 o cols] bf16, XOR-swizzled
__global__ void k_wprep(const float* __restrict__ w_conv) {
    int i = blockIdx.x * blockDim.x + threadIdx.x;
    if (i >= 9*2*64*64) return;
    int o  = i & 63;
    int ch = (i >> 6) & 63;
    int hl = (i >> 12) & 1;
    int k  = i >> 13;
    float w = w_conv[o*KIDX + ch*9 + k];
    __nv_bfloat16 hi = __float2bfloat16(w);
    unsigned short val;
    if (hl == 0) {
        val = *(unsigned short*)&hi;
    } else {
        float fhi = __bfloat162float(hi);
        __nv_bfloat16 lo = __float2bfloat16(w - fhi);
        val = *(unsigned short*)&lo;
    }
    unsigned block = (unsigned)(((k*2 + hl)*16) + (ch >> 4)*4 + (o >> 4));
    unsigned inner = (unsigned)((ch & 15)*32 + (o & 15)*2);
    inner ^= ((inner >> 7) & 1) << 4;
    *(unsigned short*)((char*)g_wB + block*512 + inner) = val;
}

// ---------------- offset-predictor 3x3 conv, pad 1, 2 px/thread ----------------
__global__ __launch_bounds__(256) void k_offconv(
    const float* __restrict__ x, const float* __restrict__ w_off,
    const float* __restrict__ b_off)
{
    extern __shared__ float sw[];   // [576][28]
    for (int i = threadIdx.x; i < CO_OFF*KIDX; i += blockDim.x) {
        int co = i / KIDX;
        int r  = i - co*KIDX;
        sw[r*28 + co] = w_off[i];
    }
    __syncthreads();

    int pix0 = blockIdx.x * 512 + threadIdx.x;
    int b  = pix0 >> 14;
    int h0 = (pix0 >> 7) & 127;
    int w0 = pix0 & 127;
    int h1 = h0 + 2;

    int   off[9];
    float vm0[9], vm1[9];
#pragma unroll
    for (int t = 0; t < 9; t++) {
        int dy = t/3 - 1, dx = t%3 - 1;
        off[t] = dy*W + dx;
        int xx = w0 + dx;
        bool vx = (xx >= 0) && (xx < W);
        int y0 = h0 + dy, y1 = h1 + dy;
        vm0[t] = (vx && y0 >= 0 && y0 < H) ? 1.f : 0.f;
        vm1[t] = (vx && y1 >= 0 && y1 < H) ? 1.f : 0.f;
    }

    u64 acc0[14], acc1[14];
#pragma unroll
    for (int j = 0; j < 13; j++) { acc0[j] = pk(b_off[2*j], b_off[2*j+1]); acc1[j] = acc0[j]; }
    acc0[13] = pk(b_off[26], 0.f); acc1[13] = acc0[13];

    const float* xc0 = x + (size_t)b*C*HW + h0*W + w0;
    const float* xc1 = xc0 + 2*W;
#pragma unroll 1
    for (int c = 0; c < C; c++) {
        float xv0[9], xv1[9];
#pragma unroll
        for (int t = 0; t < 9; t++) {
            xv0[t] = vm0[t] * __ldg(xc0 + off[t]);
            xv1[t] = vm1[t] * __ldg(xc1 + off[t]);
        }
        const float* wp = sw + c*9*28;
#pragma unroll
        for (int t = 0; t < 9; t++) {
            u64 s0 = pk(xv0[t], xv0[t]);
            u64 s1 = pk(xv1[t], xv1[t]);
#pragma unroll
            for (int j = 0; j < 7; j++) {
                float4 w4 = *(const float4*)(wp + t*28 + 4*j);
                u64 wA = pk(w4.x, w4.y);
                u64 wB = pk(w4.z, w4.w);
                acc0[2*j]   = ffma2(s0, wA, acc0[2*j]);
                acc0[2*j+1] = ffma2(s0, wB, acc0[2*j+1]);
                acc1[2*j]   = ffma2(s1, wA, acc1[2*j]);
                acc1[2*j+1] = ffma2(s1, wB, acc1[2*j+1]);
            }
        }
        xc0 += HW; xc1 += HW;
    }
    float* op0 = g_off + (size_t)b*CO_OFF*HW + h0*W + w0;
    float* op1 = op0 + 2*W;
#pragma unroll
    for (int j = 0; j < 13; j++) {
        float2 a = upk(acc0[j]); float2 bq = upk(acc1[j]);
        op0[(2*j)*HW] = a.x;  op0[(2*j+1)*HW] = a.y;
        op1[(2*j)*HW] = bq.x; op1[(2*j+1)*HW] = bq.y;
    }
    op0[26*HW] = upk(acc0[13]).x;
    op1[26*HW] = upk(acc1[13]).x;
}

// ---------------- fused: warp-specialized producer/consumer ----------------
// smem (small! leaves ~130KB L1D for gather caching):
//   [0..65536)      A ring, 2 stages x (hi 16KB + lo 16KB)
//   [65536..98304)  B ring, 2 slots x 16KB (one tap: hi 8KB + lo 8KB), cp.async-streamed
//   [98304..98336)  mbarriers: {full0, empty0, full1, empty1}
#define SMA   0
#define SMBR  65536
#define SMQ   98304
#define SMTOT 98368

__global__ __launch_bounds__(512, 1) void k_fused_ws() {
    extern __shared__ char sm[];
    const unsigned sb = smem_u32(sm);
    const int tid  = threadIdx.x;
    const int lane = tid & 31;
    const int warp = tid >> 5;

    if (tid == 0) {
        MBAR_INIT(sb + SMQ + 0,  256);   // full0  (producer threads arrive)
        MBAR_INIT(sb + SMQ + 8,  256);   // empty0 (consumer threads arrive)
        MBAR_INIT(sb + SMQ + 16, 256);   // full1
        MBAR_INIT(sb + SMQ + 24, 256);   // empty1
    }
    __syncthreads();

    int stage = 0;

    if (warp < 8) {
        // ================= PRODUCER =================
        int ph = 1;                      // first empty-wait passes immediately
        const float2* xp2 = (const float2*)g_xT;
        for (int t = blockIdx.x; t < NTILE; t += gridDim.x) {
            const int b  = t >> 7;
            const int h  = t & 127;
            const int rb = b * HW;
            const int wx = warp*16 + lane;              // lane<16 only
            const int obase0 = b*CO_OFF*HW + h*W + wx;

            // preload tap-0 offset params
            float no1 = 0.f, no2 = 0.f, nmv = 0.f;
            if (lane < 16) {
                no1 = __ldg(g_off + obase0);
                no2 = __ldg(g_off + obase0 +  9*HW);
                nmv = __ldg(g_off + obase0 + 18*HW);
            }

#pragma unroll 1
            for (int k = 0; k < 9; k++) {
                float o1 = no1, o2 = no2, mv = nmv;
                if (k < 8 && lane < 16) {               // prefetch next tap's params
                    int ob = obase0 + (k+1)*HW;
                    no1 = __ldg(g_off + ob);
                    no2 = __ldg(g_off + ob +  9*HW);
                    nmv = __ldg(g_off + ob + 18*HW);
                }

                // params for this warp's 16 px (lanes 0..15)
                float4 wt; int4 ix;
                {
                    float mask = 1.f / (1.f + expf(-mv));
                    int kh = k / 3;
                    int kw = k - kh*3;
                    float px = o1 + (float)(wx + kw - 1);
                    float py = o2 + (float)(h + kh - 1);
                    float x0f = floorf(px), y0f = floorf(py);
                    int x0 = (int)x0f, y0 = (int)y0f;
                    float wx1 = px - x0f, wy1 = py - y0f;
                    float wx0 = 1.f - wx1, wy0 = 1.f - wy1;
                    float vx0 = (x0 >= 0  && x0     < W) ? 1.f : 0.f;
                    float vx1 = (x0 >= -1 && x0 + 1 < W) ? 1.f : 0.f;
                    float vy0 = (y0 >= 0  && y0     < H) ? 1.f : 0.f;
                    float vy1 = (y0 >= -1 && y0 + 1 < H) ? 1.f : 0.f;
                    int cx0 = min(max(x0,   0), W-1);
                    int cx1 = min(max(x0+1, 0), W-1);
                    int cy0 = min(max(y0,   0), H-1);
                    int cy1 = min(max(y0+1, 0), H-1);
                    wt.x = wy0*wx0*mask*vy0*vx0;
                    wt.y = wy0*wx1*mask*vy0*vx1;
                    wt.z = wy1*wx0*mask*vy1*vx0;
                    wt.w = wy1*wx1*mask*vy1*vx1;
                    ix.x = (rb + cy0*W + cx0) << 5;   // float2 index
                    ix.y = (rb + cy0*W + cx1) << 5;
                    ix.z = (rb + cy1*W + cx0) << 5;
                    ix.w = (rb + cy1*W + cx1) << 5;
                }

                // pipelined gathers: 4-px batches, 2-batch lookahead
                float2 c[3][16];
#define P_ISSUE(bi, p4) { \
    _Pragma("unroll") \
    for (int j = 0; j < 4; j++) { \
        int pp = (p4)*4 + j; \
        int q0 = __shfl_sync(0xffffffffu, ix.x, pp); \
        int q1 = __shfl_sync(0xffffffffu, ix.y, pp); \
        int q2 = __shfl_sync(0xffffffffu, ix.z, pp); \
        int q3 = __shfl_sync(0xffffffffu, ix.w, pp); \
        c[bi][j*4+0] = xp2[q0 + lane]; \
        c[bi][j*4+1] = xp2[q1 + lane]; \
        c[bi][j*4+2] = xp2[q2 + lane]; \
        c[bi][j*4+3] = xp2[q3 + lane]; \
    } }
#define P_COMBINE(bi, p4) { \
    _Pragma("unroll") \
    for (int j = 0; j < 4; j++) { \
        int pp = (p4)*4 + j; \
        float ax = __shfl_sync(0xffffffffu, wt.x, pp); \
        float ay = __shfl_sync(0xffffffffu, wt.y, pp); \
        float az = __shfl_sync(0xffffffffu, wt.z, pp); \
        float aw = __shfl_sync(0xffffffffu, wt.w, pp); \
        u64 r = fmul2(pk(ax, ax), pk(c[bi][j*4+0].x, c[bi][j*4+0].y)); \
        r = ffma2(pk(ay, ay), pk(c[bi][j*4+1].x, c[bi][j*4+1].y), r); \
        r = ffma2(pk(az, az), pk(c[bi][j*4+2].x, c[bi][j*4+2].y), r); \
        r = ffma2(pk(aw, aw), pk(c[bi][j*4+3].x, c[bi][j*4+3].y), r); \
        float2 v = upk(r); \
        unsigned h2 = bf16x2_of(v.x, v.y); \
        float hx = __uint_as_float(h2 << 16); \
        float hy = __uint_as_float(h2 & 0xffff0000u); \
        unsigned l2 = bf16x2_of(v.x - hx, v.y - hy); \
        int pxt = warp*16 + pp; \
        unsigned boff = (unsigned)(pxt*128 + lane*4); \
        boff ^= (unsigned)((pxt & 7) << 4); \
        *(unsigned*)(aBufH + boff) = h2; \
        *(unsigned*)(aBufL + boff) = l2; \
    } }

                // issue first two batches BEFORE waiting (LDGs don't touch smem)
                P_ISSUE(0, 0);
                P_ISSUE(1, 1);
                MBAR_WAIT(sb + SMQ + stage*16 + 8, (unsigned)ph);   // empty[stage]
                char* aBufH = sm + SMA + stage*32768;
                char* aBufL = aBufH + 16384;
                P_ISSUE(2, 2);
                P_COMBINE(0, 0);
                P_ISSUE(0, 3);
                P_COMBINE(1, 1);
                P_COMBINE(2, 2);
                P_COMBINE(0, 3);
#undef P_ISSUE
#undef P_COMBINE
                MBAR_ARRIVE(sb + SMQ + stage*16);    // full[stage], release
                if (++stage == 2) { stage = 0; ph ^= 1; }
            }
        }
    } else {
        // ================= CONSUMER =================
        int ph = 0;
        const int cw  = warp - 8;
        const int pxc = cw & 3;          // 32-px chunk
        const int oh  = cw >> 2;         // 32-o half
        const unsigned a_row0 = (unsigned)((pxc*32 + (lane & 15))*128 + (lane >> 4)*16);
        const unsigned a_row1 = a_row0 + 16*128;
        const unsigned a_swz  = (unsigned)((lane & 7) << 4);
        unsigned b_inner = (unsigned)((lane & 15)*32 + (lane >> 4)*16);
        b_inner ^= ((b_inner >> 7) & 1) << 4;

        // B streaming: 2-slot ring, each thread copies its 64B of the 16KB slot
        const int ci = cw*32 + lane;                 // 0..255
        int bs = 0;                                  // current B slot
        {   // prime tap 0 into slot 0
            unsigned dst = sb + SMBR + (unsigned)ci*64;
            const char* src = (const char*)g_wB + ci*64;
#pragma unroll
            for (int j = 0; j < 4; j++) CP_ASYNC16(dst + j*16, src + j*16);
            CP_COMMIT();
        }

        for (int t = blockIdx.x; t < NTILE; t += gridDim.x) {
            const int b = t >> 7;
            const int h = t & 127;
            const int rowbase = b*HW + h*W;

            float acc[2][4][4];
#pragma unroll
            for (int m = 0; m < 2; m++)
#pragma unroll
                for (int f = 0; f < 4; f++)
#pragma unroll
                    for (int j = 0; j < 4; j++) acc[m][f][j] = 0.f;

#pragma unroll 1
            for (int k = 0; k < 9; k++) {
                MBAR_WAIT(sb + SMQ + stage*16, (unsigned)ph);     // full[stage] (A ready)
                CP_WAIT0();                                        // B_k copies done
                asm volatile("bar.sync 1, 256;" ::: "memory");     // consumer-wide visibility

                // prefetch B for next tap into the other slot (safe: all consumers
                // passed the bar, so reads of that slot from tap k-1 are complete)
                {
                    int kn = (k == 8) ? 0 : k + 1;
                    unsigned dst = sb + SMBR + (unsigned)(bs ^ 1)*16384 + (unsigned)ci*64;
                    const char* src = (const char*)g_wB + kn*16384 + ci*64;
#pragma unroll
                    for (int j = 0; j < 4; j++) CP_ASYNC16(dst + j*16, src + j*16);
                    CP_COMMIT();
                }

                const unsigned aH = sb + SMA + stage*32768;
                const unsigned aL = aH + 16384;
                const unsigned bH = sb + SMBR + (unsigned)bs*16384;
                const unsigned bL = bH + 8192;
#pragma unroll
                for (int kc = 0; kc < 4; kc++) {
                    unsigned ai0 = (a_row0 + kc*32) ^ a_swz;
                    unsigned ai1 = (a_row1 + kc*32) ^ a_swz;
                    unsigned a0h0,a0h1,a0h2,a0h3, a0l0,a0l1,a0l2,a0l3;
                    unsigned a1h0,a1h1,a1h2,a1h3, a1l0,a1l1,a1l2,a1l3;
                    ldsm_x4(a0h0,a0h1,a0h2,a0h3, aH + ai0);
                    ldsm_x4(a0l0,a0l1,a0l2,a0l3, aL + ai0);
                    ldsm_x4(a1h0,a1h1,a1h2,a1h3, aH + ai1);
                    ldsm_x4(a1l0,a1l1,a1l2,a1l3, aL + ai1);
#pragma unroll
                    for (int nb = 0; nb < 2; nb++) {
                        unsigned blk = (unsigned)(kc*4 + oh*2 + nb)*512 + b_inner;
                        unsigned bh0,bh1,bh2,bh3, bl0,bl1,bl2,bl3;
                        ldsm_x4t(bh0,bh1,bh2,bh3, bH + blk);
                        ldsm_x4t(bl0,bl1,bl2,bl3, bL + blk);
                        // m-block 0
                        mma16816(acc[0][nb*2+0], a0h0,a0h1,a0h2,a0h3, bh0,bh1);
                        mma16816(acc[0][nb*2+1], a0h0,a0h1,a0h2,a0h3, bh2,bh3);
                        mma16816(acc[0][nb*2+0], a0h0,a0h1,a0h2,a0h3, bl0,bl1);
                        mma16816(acc[0][nb*2+1], a0h0,a0h1,a0h2,a0h3, bl2,bl3);
                        mma16816(acc[0][nb*2+0], a0l0,a0l1,a0l2,a0l3, bh0,bh1);
                        mma16816(acc[0][nb*2+1], a0l0,a0l1,a0l2,a0l3, bh2,bh3);
                        // m-block 1
                        mma16816(acc[1][nb*2+0], a1h0,a1h1,a1h2,a1h3, bh0,bh1);
                        mma16816(acc[1][nb*2+1], a1h0,a1h1,a1h2,a1h3, bh2,bh3);
                        mma16816(acc[1][nb*2+0], a1h0,a1h1,a1h2,a1h3, bl0,bl1);
                        mma16816(acc[1][nb*2+1], a1h0,a1h1,a1h2,a1h3, bl2,bl3);
                        mma16816(acc[1][nb*2+0], a1l0,a1l1,a1l2,a1l3, bh0,bh1);
                        mma16816(acc[1][nb*2+1], a1l0,a1l1,a1l2,a1l3, bh2,bh3);
                    }
                }
                MBAR_ARRIVE(sb + SMQ + stage*16 + 8);   // empty[stage]
                if (++stage == 2) { stage = 0; ph ^= 1; }
                bs ^= 1;
            }

            // epilogue: registers -> g_y (NHWC)
            const int oc0 = oh*32 + 2*(lane & 3);
#pragma unroll
            for (int m = 0; m < 2; m++) {
                const int r0 = pxc*32 + m*16 + (lane >> 2);
#pragma unroll
                for (int f = 0; f < 4; f++) {
                    int oc = oc0 + (f >> 1)*16 + (f & 1)*8;
                    float* d0 = g_y + (size_t)(rowbase + r0)*64 + oc;
                    float* d1 = d0 + 8*64;
                    *(float2*)d0 = make_float2(acc[m][f][0], acc[m][f][1]);
                    *(float2*)d1 = make_float2(acc[m][f][2], acc[m][f][3]);
                }
            }
        }
    }
}

// ---------------- launch ----------------
extern "C" void kernel_launch(void* const* d_in, const int* in_sizes, int n_in,
                              void* d_out, int out_size) {
    const float* x      = (const float*)d_in[0];
    const float* w_off  = (const float*)d_in[1];
    const float* b_off  = (const float*)d_in[2];
    const float* w_conv = (const float*)d_in[3];
    float* out = (float*)d_out;

    const int smem_off = KIDX*28*(int)sizeof(float);   // 64512

    cudaFuncSetAttribute(k_offconv,  cudaFuncAttributeMaxDynamicSharedMemorySize, smem_off);
    cudaFuncSetAttribute(k_fused_ws, cudaFuncAttributeMaxDynamicSharedMemorySize, SMTOT);

    dim3 tgrid(HW/32, C/32, BB);
    dim3 tblk(32, 8);
    k_transpose_in<<<tgrid, tblk>>>(x);
    k_wprep<<<(9*2*64*64 + 255)/256, 256>>>(w_conv);
    k_offconv<<<NPIX/512, 256, smem_off>>>(x, w_off, b_off);
    k_fused_ws<<<152, 512, SMTOT>>>();
    k_transpose_out<<<tgrid, tblk>>>(out);
}